// round 14
// baseline (speedup 1.0000x reference)
#include <cuda_runtime.h>
#include <cuda_fp16.h>
#include <cstdint>
#include <math.h>

#define BEPS 1e-5f

// ---------------- scratch (static device globals; no allocation) ----------------
__device__ float g_h1[4*64*2048];
__device__ float g_h2[4*128*2048];
__device__ float g_c2sum[128], g_c2ss[128];
__device__ __align__(16) __half g_Ah[16384*128];
__device__ __align__(16) __half g_Bs[8192*128];
__device__ float g_psum[16384*64], g_pss[16384*64], g_pmx[16384*64], g_pmn[16384*64];
__device__ float g_rowstats[16384*10];
__device__ float g_u[4*1024*16];
__device__ __align__(16) __half g_uhat_h[(long)4*64*1024*64]; // 33.5MB [b][l][p][v]
__device__ float g_bij[4*64*1024];
__device__ float g_norm[4096*2];
__device__ float g_vj[4*64*64];
__device__ unsigned int g_cnt = 0;
__device__ volatile unsigned int g_gen = 0;

__device__ __forceinline__ uint32_t smem_u32(const void* p) {
    uint32_t a;
    asm("{ .reg .u64 t; cvta.to.shared.u64 t, %1; cvt.u32.u64 %0, t; }" : "=r"(a) : "l"(p));
    return a;
}
__device__ __forceinline__ void cp16(uint32_t dst, const void* src) {
    asm volatile("cp.async.cg.shared.global [%0], [%1], 16;" :: "r"(dst), "l"(src));
}
#define CP_COMMIT() asm volatile("cp.async.commit_group;" ::: "memory")
#define CP_WAIT(n)  asm volatile("cp.async.wait_group %0;" :: "n"(n) : "memory")

__device__ __forceinline__ void ldsm4(uint32_t* r, uint32_t addr) {
    asm volatile("ldmatrix.sync.aligned.m8n8.x4.shared.b16 {%0,%1,%2,%3}, [%4];"
        : "=r"(r[0]), "=r"(r[1]), "=r"(r[2]), "=r"(r[3]) : "r"(addr));
}
__device__ __forceinline__ void mma16816(float* d, const uint32_t* a, const uint32_t* b) {
    asm volatile("mma.sync.aligned.m16n8k16.row.col.f32.f16.f16.f32 "
        "{%0,%1,%2,%3}, {%4,%5,%6,%7}, {%8,%9}, {%0,%1,%2,%3};"
        : "+f"(d[0]), "+f"(d[1]), "+f"(d[2]), "+f"(d[3])
        : "r"(a[0]), "r"(a[1]), "r"(a[2]), "r"(a[3]), "r"(b[0]), "r"(b[1]));
}

// grid-wide barrier (all nb blocks co-resident; deterministic)
__device__ __forceinline__ void gsync(unsigned int nb) {
    __threadfence();
    __syncthreads();
    if (threadIdx.x == 0) {
        unsigned int my = g_gen;
        if (atomicAdd(&g_cnt, 1u) == nb - 1u) {
            g_cnt = 0;
            __threadfence();
            g_gen = my + 1u;
        } else {
            while (g_gen == my) { }
        }
    }
    __syncthreads();
}

// ---------------- front: conv1(+inline bn1) | cast w3 | zero bij/c2 ----------
__global__ void __launch_bounds__(256) k_front(const float* __restrict__ x,
        const float* __restrict__ w1, const float* __restrict__ b1,
        const float* __restrict__ g1, const float* __restrict__ be1,
        const float* __restrict__ w3) {
    int blk = blockIdx.x, t = threadIdx.x;
    if (blk < 128) {
        int nb = blk & 7, b = (blk >> 3) & 3, og = (blk >> 5) * 16;
        __shared__ float red[9][8];
        __shared__ float m[3], cov[3][3];
        __shared__ float ssc[16], ssh[16];
        float s0=0,s1=0,s2=0,p00=0,p01=0,p02=0,p11=0,p12=0,p22=0;
        for (int i = t; i < 8192; i += 256) {
            int bb = i >> 11, n = i & 2047;
            const float* xb = x + bb*3*2048 + n;
            float a = xb[0], c = xb[2048], d = xb[4096];
            s0+=a; s1+=c; s2+=d;
            p00+=a*a; p01+=a*c; p02+=a*d; p11+=c*c; p12+=c*d; p22+=d*d;
        }
        float vals[9] = {s0,s1,s2,p00,p01,p02,p11,p12,p22};
        int lane = t & 31, w = t >> 5;
        #pragma unroll
        for (int j=0;j<9;j++) {
            float v = vals[j];
            #pragma unroll
            for (int o=16;o>0;o>>=1) v += __shfl_down_sync(0xffffffffu, v, o);
            if (lane==0) red[j][w] = v;
        }
        __syncthreads();
        if (t < 9) {
            float v = 0;
            for (int ww=0; ww<8; ww++) v += red[t][ww];
            red[t][0] = v * (1.f/8192.f);
        }
        __syncthreads();
        if (t == 0) {
            m[0]=red[0][0]; m[1]=red[1][0]; m[2]=red[2][0];
            cov[0][0]=red[3][0]-m[0]*m[0];
            cov[0][1]=cov[1][0]=red[4][0]-m[0]*m[1];
            cov[0][2]=cov[2][0]=red[5][0]-m[0]*m[2];
            cov[1][1]=red[6][0]-m[1]*m[1];
            cov[1][2]=cov[2][1]=red[7][0]-m[1]*m[2];
            cov[2][2]=red[8][0]-m[2]*m[2];
        }
        __syncthreads();
        if (t < 16) {
            int o = og + t;
            float wv0=w1[o*3], wv1=w1[o*3+1], wv2=w1[o*3+2];
            float mean = wv0*m[0]+wv1*m[1]+wv2*m[2] + b1[o];
            float var = wv0*wv0*cov[0][0] + wv1*wv1*cov[1][1] + wv2*wv2*cov[2][2]
                      + 2.f*(wv0*wv1*cov[0][1] + wv0*wv2*cov[0][2] + wv1*wv2*cov[1][2]);
            float sc = g1[o]*rsqrtf(var + BEPS);
            ssc[t] = sc;
            ssh[t] = be1[o] - mean*sc;
        }
        __syncthreads();
        int n = nb*256 + t;
        float x0 = x[b*6144 + n], x1 = x[b*6144 + 2048 + n], x2 = x[b*6144 + 4096 + n];
        #pragma unroll
        for (int oo=0;oo<16;oo++) {
            int o = og + oo;
            float pre = fmaf(w1[o*3], x0, fmaf(w1[o*3+1], x1, fmaf(w1[o*3+2], x2, b1[o])));
            float h = fmaf(ssc[oo], pre, ssh[oo]);
            g_h1[(b*64+o)*2048 + n] = fmaxf(h, 0.f);
        }
    } else if (blk < 2176) {
        int blk2 = blk - 128;
        #pragma unroll
        for (int i=0;i<4;i++) {
            int id = blk2*1024 + i*256 + t;
            g_Ah[id] = __float2half_rn(w3[id]);
        }
    } else if (blk < 2432) {
        int blk3 = blk - 2176;
        #pragma unroll
        for (int i=0;i<4;i++) g_bij[blk3*1024 + i*256 + t] = 0.f;
    } else {
        if (t < 128) { g_c2sum[t] = 0.f; g_c2ss[t] = 0.f; }
    }
}

// ---------------- conv2 + BN2 + relu + transpose -> B fp16, one persistent kernel
__global__ void __launch_bounds__(256) k_conv2sb(const float* __restrict__ w2,
        const float* __restrict__ b2, const float* __restrict__ g2,
        const float* __restrict__ be2) {
    __shared__ float sbuf[8576];
    int blk = blockIdx.x, t = threadIdx.x;

    {
        float (*As)[128] = (float(*)[128])sbuf;
        float (*Bs)[128] = (float(*)[128])(sbuf + 4096);
        float* s_sum = sbuf + 8192;
        float* s_ss  = sbuf + 8320;
        int b = blk >> 4, n0 = (blk & 15)*128;
        int tx = t & 15, ty = t >> 4;
        float acc[8][8];
        #pragma unroll
        for (int r=0;r<8;r++)
            #pragma unroll
            for (int c=0;c<8;c++) acc[r][c] = 0.f;
        if (t < 128) { s_sum[t] = 0.f; s_ss[t] = 0.f; }
        for (int kc = 0; kc < 64; kc += 32) {
            __syncthreads();
            #pragma unroll
            for (int i=0;i<16;i++) { int f=t+i*256; int k=f>>7, o=f&127; As[k][o] = w2[o*64 + kc + k]; }
            #pragma unroll
            for (int i=0;i<16;i++) { int f=t+i*256; int k=f>>7, n=f&127;
                Bs[k][n] = g_h1[(b*64 + kc + k)*2048 + n0 + n]; }
            __syncthreads();
            #pragma unroll
            for (int k=0;k<32;k++) {
                float a[8], bb[8];
                *(float4*)&a[0]  = *(const float4*)&As[k][ty*8];
                *(float4*)&a[4]  = *(const float4*)&As[k][ty*8+4];
                *(float4*)&bb[0] = *(const float4*)&Bs[k][tx*8];
                *(float4*)&bb[4] = *(const float4*)&Bs[k][tx*8+4];
                #pragma unroll
                for (int r=0;r<8;r++)
                    #pragma unroll
                    for (int c=0;c<8;c++) acc[r][c] = fmaf(a[r], bb[c], acc[r][c]);
            }
        }
        #pragma unroll
        for (int r=0;r<8;r++) {
            int o = ty*8 + r;
            float bias = b2[o];
            float rs = 0.f, rq = 0.f;
            float v[8];
            #pragma unroll
            for (int c=0;c<8;c++) { v[c] = acc[r][c] + bias; rs += v[c]; rq = fmaf(v[c], v[c], rq); }
            float* dst = &g_h2[(b*128+o)*2048 + n0 + tx*8];
            *(float4*)dst     = *(float4*)&v[0];
            *(float4*)(dst+4) = *(float4*)&v[4];
            atomicAdd(&s_sum[o], rs);
            atomicAdd(&s_ss[o], rq);
        }
        __syncthreads();
        if (t < 128) { atomicAdd(&g_c2sum[t], s_sum[t]); atomicAdd(&g_c2ss[t], s_ss[t]); }
    }
    gsync(64);

    {
        float (*smv)[65] = (float(*)[65])sbuf;
        float* ssc = sbuf + 8320;
        float* ssh = sbuf + 8448;
        if (t < 128) {
            float mean = g_c2sum[t] * (1.f/8192.f);
            float var = g_c2ss[t] * (1.f/8192.f) - mean*mean;
            float sc = g2[t]*rsqrtf(var + BEPS);
            ssc[t] = sc;
            ssh[t] = be2[t] - mean*sc;
        }
        __syncthreads();
        #pragma unroll
        for (int inst_i = 0; inst_i < 2; inst_i++) {
            int inst = blk*2 + inst_i;
            int b = inst >> 5, n0 = (inst & 31)*64;
            #pragma unroll
            for (int i=0;i<32;i++) {
                int f = t + i*256; int c = f >> 6, n = f & 63;
                float v = g_h2[(b*128+c)*2048 + n0 + n];
                smv[c][n] = fmaxf(fmaf(ssc[c], v, ssh[c]), 0.f);
            }
            __syncthreads();
            int col = t & 63, q = t >> 6;
            __half* dst = g_Bs + (size_t)(b*2048 + n0 + col)*128;
            #pragma unroll
            for (int ch=0; ch<32; ch++)
                dst[q*32+ch] = __float2half_rn(smv[q*32+ch][col]);
            __syncthreads();
        }
    }
}

// ---------------- caps GEMM via mma.sync fp16: D = A · B^T, K=128 --------------
#define LDAH 136
#define A_BYTES (128*LDAH*2)
#define CAPS_SMEM (2*A_BYTES)

__global__ void __launch_bounds__(256,2) k_caps_mma() {
    extern __shared__ char sm[];
    const uint32_t sb = smem_u32(sm);
    const int t = threadIdx.x, w = t >> 5, lane = t & 31;
    const int row0 = blockIdx.y * 128, col0 = blockIdx.x * 128;
    const int wm = (w >> 1) * 32, wn = (w & 1) * 64;
    const int lr = lane & 7, mi = lane >> 3;

    const uint32_t aoff = ((uint32_t)(wm + (mi&1)*8 + lr)*LDAH + (mi>>1)*8) * 2;
    const uint32_t boff = ((uint32_t)(wn + (mi>>1)*8 + lr)*LDAH + (mi&1)*8) * 2;

    #pragma unroll
    for (int i=0;i<8;i++) {
        int idx = t + i*256; int r = idx >> 4, j = idx & 15;
        cp16(sb + (uint32_t)(r*LDAH)*2 + j*16,
             g_Ah + (size_t)(row0 + r)*128 + j*8);
    }
    #pragma unroll
    for (int i=0;i<8;i++) {
        int idx = t + i*256; int r = idx >> 4, j = idx & 15;
        cp16(sb + A_BYTES + (uint32_t)(r*LDAH)*2 + j*16,
             g_Bs + (size_t)(col0 + r)*128 + j*8);
    }
    CP_COMMIT();

    float acc[2][8][4];
    #pragma unroll
    for (int mt=0;mt<2;mt++)
        #pragma unroll
        for (int nt=0;nt<8;nt++)
            #pragma unroll
            for (int e=0;e<4;e++) acc[mt][nt][e] = 0.f;

    CP_WAIT(0);
    __syncthreads();

    #pragma unroll
    for (int ks=0; ks<8; ks++) {
        uint32_t a[2][4];
        #pragma unroll
        for (int mt=0;mt<2;mt++)
            ldsm4(a[mt], sb + aoff + (uint32_t)(mt*16*LDAH)*2 + ks*32);
        #pragma unroll
        for (int ntp=0;ntp<4;ntp++) {
            uint32_t b[4];
            ldsm4(b, sb + A_BYTES + boff + (uint32_t)(ntp*16*LDAH)*2 + ks*32);
            #pragma unroll
            for (int mt=0;mt<2;mt++) {
                mma16816(acc[mt][ntp*2],   a[mt], b);
                mma16816(acc[mt][ntp*2+1], a[mt], b+2);
            }
        }
    }
    __syncthreads();

    float4* cmb = (float4*)sm;
    #pragma unroll
    for (int mt=0;mt<2;mt++) {
        float s0=0.f,q0=0.f,mx0=-3.4028235e38f,mn0=3.4028235e38f;
        float s1=0.f,q1=0.f,mx1=-3.4028235e38f,mn1=3.4028235e38f;
        #pragma unroll
        for (int nt=0;nt<8;nt++) {
            float d0=acc[mt][nt][0], d1=acc[mt][nt][1];
            float d2=acc[mt][nt][2], d3=acc[mt][nt][3];
            s0 += d0+d1; q0 = fmaf(d0,d0,fmaf(d1,d1,q0));
            mx0 = fmaxf(mx0, fmaxf(d0,d1)); mn0 = fminf(mn0, fminf(d0,d1));
            s1 += d2+d3; q1 = fmaf(d2,d2,fmaf(d3,d3,q1));
            mx1 = fmaxf(mx1, fmaxf(d2,d3)); mn1 = fminf(mn1, fminf(d2,d3));
        }
        #pragma unroll
        for (int o=1;o<4;o<<=1) {
            s0 += __shfl_xor_sync(0xffffffffu, s0, o);
            q0 += __shfl_xor_sync(0xffffffffu, q0, o);
            mx0 = fmaxf(mx0, __shfl_xor_sync(0xffffffffu, mx0, o));
            mn0 = fminf(mn0, __shfl_xor_sync(0xffffffffu, mn0, o));
            s1 += __shfl_xor_sync(0xffffffffu, s1, o);
            q1 += __shfl_xor_sync(0xffffffffu, q1, o);
            mx1 = fmaxf(mx1, __shfl_xor_sync(0xffffffffu, mx1, o));
            mn1 = fminf(mn1, __shfl_xor_sync(0xffffffffu, mn1, o));
        }
        if ((lane & 3) == 0) {
            int r0 = wm + mt*16 + (lane >> 2);
            cmb[r0*2 + (w&1)]     = make_float4(s0, q0, mx0, mn0);
            cmb[(r0+8)*2 + (w&1)] = make_float4(s1, q1, mx1, mn1);
        }
    }
    __syncthreads();
    if (t < 128) {
        float4 a = cmb[t*2+0], b = cmb[t*2+1];
        int gi = (row0 + t)*64 + blockIdx.x;
        g_psum[gi] = a.x+b.x;
        g_pss[gi]  = a.y+b.y;
        g_pmx[gi]  = fmaxf(a.z,b.z);
        g_pmn[gi]  = fminf(a.w,b.w);
    }
}

// ---------------- redstats + ufin, 64 persistent blocks ----------------
__global__ void __launch_bounds__(256) k_redufin(const float* __restrict__ b3,
        const float* __restrict__ g3, const float* __restrict__ be3) {
    int bid = blockIdx.x, t = threadIdx.x;
    {
        int row = bid*256 + t;
        float s = 0.f, q = 0.f;
        float mx[4], mn[4];
        #pragma unroll
        for (int b=0;b<4;b++) { mx[b] = -3.4028235e38f; mn[b] = 3.4028235e38f; }
        #pragma unroll
        for (int nt=0; nt<64; nt++) {
            int gi = row*64 + nt, b = nt >> 4;
            s += g_psum[gi]; q += g_pss[gi];
            mx[b] = fmaxf(mx[b], g_pmx[gi]);
            mn[b] = fminf(mn[b], g_pmn[gi]);
        }
        float bias = b3[row];
        float sv = s + 8192.f*bias;
        float qv = q + 2.f*bias*s + 8192.f*bias*bias;
        float* o = g_rowstats + row*10;
        o[0] = sv; o[1] = qv;
        #pragma unroll
        for (int b=0;b<4;b++) { o[2+b] = mx[b] + bias; o[6+b] = mn[b] + bias; }
    }
    gsync(64);
    {
        int idx = bid*64 + (t >> 2);            // 4096 items, 4 threads each
        int qq = t & 3;
        int b = idx >> 10, p = idx & 1023;
        float vq[4]; float sn = 0.f;
        #pragma unroll
        for (int qi=0;qi<4;qi++) {
            int row = (qq*4+qi)*1024 + p;
            const float* st = g_rowstats + row*10;
            float mean = st[0]*(1.f/8192.f);
            float var  = st[1]*(1.f/8192.f) - mean*mean;
            float sc = g3[row]*rsqrtf(var + BEPS);
            float m = (sc >= 0.f) ? st[2+b] : st[6+b];
            float v = fmaf(sc, m - mean, be3[row]);
            vq[qi] = v; sn = fmaf(v,v,sn);
        }
        #pragma unroll
        for (int o=1;o<4;o<<=1) sn += __shfl_xor_sync(0xffffffffu, sn, o);
        float coef = sn/((1.f+sn)*sqrtf(sn));
        #pragma unroll
        for (int qi=0;qi<4;qi++) g_u[(b*1024+p)*16 + qq*4+qi] = coef*vq[qi];
    }
}

// ---------------- u_hat = einsum(lpvq,bpq->blpv), fp16, big grid ----------------
__global__ void __launch_bounds__(256) k_uhat(const float* __restrict__ Wr) {
    int gid = blockIdx.x*256 + threadIdx.x;   // 262144
    int lp = gid >> 2, vg = gid & 3;
    int l = lp >> 10, p = lp & 1023;
    float u0[16], u1[16], u2[16], u3[16];
    #pragma unroll
    for (int j=0;j<4;j++) {
        *(float4*)&u0[j*4] = *(const float4*)&g_u[(0*1024+p)*16 + j*4];
        *(float4*)&u1[j*4] = *(const float4*)&g_u[(1*1024+p)*16 + j*4];
        *(float4*)&u2[j*4] = *(const float4*)&g_u[(2*1024+p)*16 + j*4];
        *(float4*)&u3[j*4] = *(const float4*)&g_u[(3*1024+p)*16 + j*4];
    }
    const float4* wr = (const float4*)(Wr + (size_t)lp*1024 + vg*256);
    size_t obase = (((size_t)l*1024 + p)*64 + vg*16) >> 3;   // uint4 units
    uint4* o0 = (uint4*)g_uhat_h + obase;
    uint4* o1 = (uint4*)g_uhat_h + ((size_t)64*1024*64 >> 3) + obase;
    uint4* o2 = (uint4*)g_uhat_h + ((size_t)2*64*1024*64 >> 3) + obase;
    uint4* o3 = (uint4*)g_uhat_h + ((size_t)3*64*1024*64 >> 3) + obase;
    #pragma unroll
    for (int vc = 0; vc < 2; vc++) {          // 8 v per chunk
        uint32_t pk0[4], pk1[4], pk2[4], pk3[4];
        #pragma unroll
        for (int v2 = 0; v2 < 4; v2++) {
            float da[4], db[4];
            #pragma unroll
            for (int h = 0; h < 2; h++) {
                int v = vc*8 + v2*2 + h;
                float wv[16];
                *(float4*)&wv[0]  = wr[v*4+0];
                *(float4*)&wv[4]  = wr[v*4+1];
                *(float4*)&wv[8]  = wr[v*4+2];
                *(float4*)&wv[12] = wr[v*4+3];
                float d0=0.f, d1=0.f, d2=0.f, d3=0.f;
                #pragma unroll
                for (int q=0;q<16;q++) {
                    d0 = fmaf(wv[q], u0[q], d0);
                    d1 = fmaf(wv[q], u1[q], d1);
                    d2 = fmaf(wv[q], u2[q], d2);
                    d3 = fmaf(wv[q], u3[q], d3);
                }
                if (h == 0) { da[0]=d0; da[1]=d1; da[2]=d2; da[3]=d3; }
                else        { db[0]=d0; db[1]=d1; db[2]=d2; db[3]=d3; }
            }
            __half2 h0 = __floats2half2_rn(da[0], db[0]);
            __half2 h1 = __floats2half2_rn(da[1], db[1]);
            __half2 h2 = __floats2half2_rn(da[2], db[2]);
            __half2 h3 = __floats2half2_rn(da[3], db[3]);
            pk0[v2] = *(uint32_t*)&h0; pk1[v2] = *(uint32_t*)&h1;
            pk2[v2] = *(uint32_t*)&h2; pk3[v2] = *(uint32_t*)&h3;
        }
        o0[vc] = make_uint4(pk0[0],pk0[1],pk0[2],pk0[3]);
        o1[vc] = make_uint4(pk1[0],pk1[1],pk1[2],pk1[3]);
        o2[vc] = make_uint4(pk2[0],pk2[1],pk2[2],pk2[3]);
        o3[vc] = make_uint4(pk3[0],pk3[1],pk3[2],pk3[3]);
    }
}

// ---------------- persistent routing + heads ----------------
__global__ void __launch_bounds__(256) k_route(const float* __restrict__ fcw,
        const float* __restrict__ fcb, float* __restrict__ out) {
    int bid = blockIdx.x, t = threadIdx.x;
    __shared__ float cs[1024];
    __shared__ float red[8][64];
    __shared__ float sq[64];
    __shared__ float s_coef;
    __shared__ float vs[64];

    int b = bid >> 6, l = bid & 63;
    const __half2* uh = (const __half2*)(g_uhat_h + ((long)(b*64+l))*65536);
    float* bp = g_bij + (b*64+l)*1024;

    for (int it = 0; it < 3; it++) {
        {
            int item = bid*16 + (t >> 4);
            int sub = t & 15;
            int bb = item >> 10, pp = item & 1023;
            const float* bcol = g_bij + bb*65536 + pp;
            float v0 = bcol[(sub*4+0)*1024];
            float v1 = bcol[(sub*4+1)*1024];
            float v2 = bcol[(sub*4+2)*1024];
            float v3 = bcol[(sub*4+3)*1024];
            float mx = fmaxf(fmaxf(v0,v1), fmaxf(v2,v3));
            #pragma unroll
            for (int o=8;o>0;o>>=1) mx = fmaxf(mx, __shfl_down_sync(0xffffffffu, mx, o, 16));
            mx = __shfl_sync(0xffffffffu, mx, 0, 16);
            float s = __expf(v0-mx)+__expf(v1-mx)+__expf(v2-mx)+__expf(v3-mx);
            #pragma unroll
            for (int o=8;o>0;o>>=1) s += __shfl_down_sync(0xffffffffu, s, o, 16);
            if (sub == 0) { g_norm[item*2] = mx; g_norm[item*2+1] = 1.f/s; }
        }
        gsync(256);

        {
            int j = t & 31, pc = t >> 5;
            for (int i=t;i<1024;i+=256) {
                float bv = bp[i];
                float mx = g_norm[(b*1024+i)*2], inv = g_norm[(b*1024+i)*2+1];
                cs[i] = __expf(bv - mx) * inv;
            }
            __syncthreads();
            float2 a0 = {0.f,0.f}, a1 = {0.f,0.f};
            int pb = pc*128;
            #pragma unroll 4
            for (int p = pb; p < pb+128; p += 2) {
                float2 h0 = __half22float2(uh[p*32 + j]);
                float2 h1 = __half22float2(uh[(p+1)*32 + j]);
                float c0 = cs[p], c1 = cs[p+1];
                a0.x = fmaf(c0, h0.x, a0.x); a0.y = fmaf(c0, h0.y, a0.y);
                a1.x = fmaf(c1, h1.x, a1.x); a1.y = fmaf(c1, h1.y, a1.y);
            }
            red[pc][2*j]   = a0.x + a1.x;
            red[pc][2*j+1] = a0.y + a1.y;
            __syncthreads();
            if (t < 64) {
                float vr = 0.f;
                #pragma unroll
                for (int k=0;k<8;k++) vr += red[k][t];
                red[0][t] = vr;
                sq[t] = vr*vr;
            }
            __syncthreads();
            if (t == 0) {
                float sn = 0.f;
                for (int i=0;i<64;i++) sn += sq[i];
                s_coef = sn/((1.f+sn)*sqrtf(sn));
            }
            __syncthreads();
            if (t < 64) {
                float vv = s_coef*red[0][t];
                vs[t] = vv;
                if (it == 2) g_vj[(b*64+l)*64 + t] = vv;
            }
            __syncthreads();
        }
        if (it < 2) {
            #pragma unroll
            for (int p4 = 0; p4 < 4; p4++) {
                int p = t*4 + p4;
                const __half2* row = uh + p*32;
                float a = 0.f;
                #pragma unroll 8
                for (int j = 0; j < 32; j++) {
                    float2 h = __half22float2(row[j]);
                    a = fmaf(vs[2*j], h.x, fmaf(vs[2*j+1], h.y, a));
                }
                bp[p] += a;
            }
        }
        gsync(256);
    }

    if (bid < 160) {
        int bo = bid/40, o = bid%40;
        const float* vj = g_vj + bo*4096;
        const float* wr = fcw + o*4096;
        float acc = 0.f;
        for (int i=t;i<4096;i+=256) acc = fmaf(vj[i], wr[i], acc);
        #pragma unroll
        for (int off=16;off>0;off>>=1) acc += __shfl_down_sync(0xffffffffu, acc, off);
        if ((t&31)==0) sq[t>>5] = acc;
        __syncthreads();
        if (t==0) {
            float r = 0.f;
            #pragma unroll
            for (int k=0;k<8;k++) r += sq[k];
            out[bo*40+o] = r + fcb[o];
        }
    } else if (bid < 224) {
        int w = t >> 5, lane = t & 31;
        int item = (bid-160)*4 + (w >> 1), half = w & 1;
        float v = g_vj[item*64 + half*32 + lane];
        float sv = v*v;
        #pragma unroll
        for (int off=16;off>0;off>>=1) sv += __shfl_down_sync(0xffffffffu, sv, off);
        if (lane==0) red[0][w] = sv;
        __syncthreads();
        if (t < 4) out[160 + (bid-160)*4 + t] = sqrtf(red[0][2*t] + red[0][2*t+1]);
    }
}

// ---------------- launch ----------------
extern "C" void kernel_launch(void* const* d_in, const int* in_sizes, int n_in,
                              void* d_out, int out_size) {
    const float* x   = (const float*)d_in[0];
    const float* w1  = (const float*)d_in[1];
    const float* b1  = (const float*)d_in[2];
    const float* g1  = (const float*)d_in[3];
    const float* be1 = (const float*)d_in[4];
    const float* w2  = (const float*)d_in[5];
    const float* b2  = (const float*)d_in[6];
    const float* g2  = (const float*)d_in[7];
    const float* be2 = (const float*)d_in[8];
    const float* w3  = (const float*)d_in[9];
    const float* b3  = (const float*)d_in[10];
    const float* g3  = (const float*)d_in[11];
    const float* be3 = (const float*)d_in[12];
    const float* Wr  = (const float*)d_in[13];
    const float* fcw = (const float*)d_in[14];
    const float* fcb = (const float*)d_in[15];
    float* out = (float*)d_out;

    cudaFuncSetAttribute(k_caps_mma, cudaFuncAttributeMaxDynamicSharedMemorySize, CAPS_SMEM);

    k_front<<<2433,256>>>(x,w1,b1,g1,be1,w3);          // launch 0
    k_conv2sb<<<64,256>>>(w2,b2,g2,be2);               // launch 1
    k_caps_mma<<<dim3(64,128),256,CAPS_SMEM>>>();      // launch 2
    k_redufin<<<64,256>>>(b3,g3,be3);                  // launch 3
    k_uhat<<<1024,256>>>(Wr);                          // launch 4
    k_route<<<256,256>>>(fcw,fcb,out);                 // launch 5
}

// round 15
// speedup vs baseline: 1.0641x; 1.0641x over previous
#include <cuda_runtime.h>
#include <cuda_fp16.h>
#include <cstdint>
#include <math.h>

#define BEPS 1e-5f

// ---------------- scratch (static device globals; no allocation) ----------------
__device__ float g_h1[4*64*2048];
__device__ float g_h2[4*128*2048];
__device__ float g_c2sum[128], g_c2ss[128];
__device__ __align__(16) __half g_Ah[16384*128];
__device__ __align__(16) __half g_Bs[8192*128];
__device__ float g_psum[16384*64], g_pss[16384*64], g_pmx[16384*64], g_pmn[16384*64];
__device__ float g_rowstats[16384*10];
__device__ float g_u[4*1024*16];
__device__ __align__(16) __half g_uhat_h[(long)4*64*1024*64]; // 33.5MB [b][l][p][v]
__device__ float g_bij[4*64*1024];
__device__ float g_norm[4096*2];
__device__ float g_vj[4*64*64];
__device__ unsigned int g_cnt = 0;
__device__ volatile unsigned int g_gen = 0;

__device__ __forceinline__ uint32_t smem_u32(const void* p) {
    uint32_t a;
    asm("{ .reg .u64 t; cvta.to.shared.u64 t, %1; cvt.u32.u64 %0, t; }" : "=r"(a) : "l"(p));
    return a;
}
__device__ __forceinline__ void cp16(uint32_t dst, const void* src) {
    asm volatile("cp.async.cg.shared.global [%0], [%1], 16;" :: "r"(dst), "l"(src));
}
#define CP_COMMIT() asm volatile("cp.async.commit_group;" ::: "memory")
#define CP_WAIT(n)  asm volatile("cp.async.wait_group %0;" :: "n"(n) : "memory")

__device__ __forceinline__ void ldsm4(uint32_t* r, uint32_t addr) {
    asm volatile("ldmatrix.sync.aligned.m8n8.x4.shared.b16 {%0,%1,%2,%3}, [%4];"
        : "=r"(r[0]), "=r"(r[1]), "=r"(r[2]), "=r"(r[3]) : "r"(addr));
}
__device__ __forceinline__ void mma16816(float* d, const uint32_t* a, const uint32_t* b) {
    asm volatile("mma.sync.aligned.m16n8k16.row.col.f32.f16.f16.f32 "
        "{%0,%1,%2,%3}, {%4,%5,%6,%7}, {%8,%9}, {%0,%1,%2,%3};"
        : "+f"(d[0]), "+f"(d[1]), "+f"(d[2]), "+f"(d[3])
        : "r"(a[0]), "r"(a[1]), "r"(a[2]), "r"(a[3]), "r"(b[0]), "r"(b[1]));
}

// grid-wide barrier (all nb blocks co-resident; deterministic)
__device__ __forceinline__ void gsync(unsigned int nb) {
    __threadfence();
    __syncthreads();
    if (threadIdx.x == 0) {
        unsigned int my = g_gen;
        if (atomicAdd(&g_cnt, 1u) == nb - 1u) {
            g_cnt = 0;
            __threadfence();
            g_gen = my + 1u;
        } else {
            while (g_gen == my) { }
        }
    }
    __syncthreads();
}

// ---------------- front: conv1(+inline bn1) | cast w3 | zero bij/c2 ----------
__global__ void __launch_bounds__(256) k_front(const float* __restrict__ x,
        const float* __restrict__ w1, const float* __restrict__ b1,
        const float* __restrict__ g1, const float* __restrict__ be1,
        const float* __restrict__ w3) {
    int blk = blockIdx.x, t = threadIdx.x;
    if (blk < 128) {
        int nb = blk & 7, b = (blk >> 3) & 3, og = (blk >> 5) * 16;
        __shared__ float red[9][8];
        __shared__ float m[3], cov[3][3];
        __shared__ float ssc[16], ssh[16];
        float s0=0,s1=0,s2=0,p00=0,p01=0,p02=0,p11=0,p12=0,p22=0;
        for (int i = t; i < 8192; i += 256) {
            int bb = i >> 11, n = i & 2047;
            const float* xb = x + bb*3*2048 + n;
            float a = xb[0], c = xb[2048], d = xb[4096];
            s0+=a; s1+=c; s2+=d;
            p00+=a*a; p01+=a*c; p02+=a*d; p11+=c*c; p12+=c*d; p22+=d*d;
        }
        float vals[9] = {s0,s1,s2,p00,p01,p02,p11,p12,p22};
        int lane = t & 31, w = t >> 5;
        #pragma unroll
        for (int j=0;j<9;j++) {
            float v = vals[j];
            #pragma unroll
            for (int o=16;o>0;o>>=1) v += __shfl_down_sync(0xffffffffu, v, o);
            if (lane==0) red[j][w] = v;
        }
        __syncthreads();
        if (t < 9) {
            float v = 0;
            for (int ww=0; ww<8; ww++) v += red[t][ww];
            red[t][0] = v * (1.f/8192.f);
        }
        __syncthreads();
        if (t == 0) {
            m[0]=red[0][0]; m[1]=red[1][0]; m[2]=red[2][0];
            cov[0][0]=red[3][0]-m[0]*m[0];
            cov[0][1]=cov[1][0]=red[4][0]-m[0]*m[1];
            cov[0][2]=cov[2][0]=red[5][0]-m[0]*m[2];
            cov[1][1]=red[6][0]-m[1]*m[1];
            cov[1][2]=cov[2][1]=red[7][0]-m[1]*m[2];
            cov[2][2]=red[8][0]-m[2]*m[2];
        }
        __syncthreads();
        if (t < 16) {
            int o = og + t;
            float wv0=w1[o*3], wv1=w1[o*3+1], wv2=w1[o*3+2];
            float mean = wv0*m[0]+wv1*m[1]+wv2*m[2] + b1[o];
            float var = wv0*wv0*cov[0][0] + wv1*wv1*cov[1][1] + wv2*wv2*cov[2][2]
                      + 2.f*(wv0*wv1*cov[0][1] + wv0*wv2*cov[0][2] + wv1*wv2*cov[1][2]);
            float sc = g1[o]*rsqrtf(var + BEPS);
            ssc[t] = sc;
            ssh[t] = be1[o] - mean*sc;
        }
        __syncthreads();
        int n = nb*256 + t;
        float x0 = x[b*6144 + n], x1 = x[b*6144 + 2048 + n], x2 = x[b*6144 + 4096 + n];
        #pragma unroll
        for (int oo=0;oo<16;oo++) {
            int o = og + oo;
            float pre = fmaf(w1[o*3], x0, fmaf(w1[o*3+1], x1, fmaf(w1[o*3+2], x2, b1[o])));
            float h = fmaf(ssc[oo], pre, ssh[oo]);
            g_h1[(b*64+o)*2048 + n] = fmaxf(h, 0.f);
        }
    } else if (blk < 2176) {
        int blk2 = blk - 128;
        #pragma unroll
        for (int i=0;i<4;i++) {
            int id = blk2*1024 + i*256 + t;
            g_Ah[id] = __float2half_rn(w3[id]);
        }
    } else if (blk < 2432) {
        int blk3 = blk - 2176;
        #pragma unroll
        for (int i=0;i<4;i++) g_bij[blk3*1024 + i*256 + t] = 0.f;
    } else {
        if (t < 128) { g_c2sum[t] = 0.f; g_c2ss[t] = 0.f; }
    }
}

// ---------------- conv2 + BN2 + relu + transpose -> B fp16, one persistent kernel
__global__ void __launch_bounds__(256) k_conv2sb(const float* __restrict__ w2,
        const float* __restrict__ b2, const float* __restrict__ g2,
        const float* __restrict__ be2) {
    __shared__ float sbuf[8576];
    int blk = blockIdx.x, t = threadIdx.x;

    {
        float (*As)[128] = (float(*)[128])sbuf;
        float (*Bs)[128] = (float(*)[128])(sbuf + 4096);
        float* s_sum = sbuf + 8192;
        float* s_ss  = sbuf + 8320;
        int b = blk >> 4, n0 = (blk & 15)*128;
        int tx = t & 15, ty = t >> 4;
        float acc[8][8];
        #pragma unroll
        for (int r=0;r<8;r++)
            #pragma unroll
            for (int c=0;c<8;c++) acc[r][c] = 0.f;
        if (t < 128) { s_sum[t] = 0.f; s_ss[t] = 0.f; }
        for (int kc = 0; kc < 64; kc += 32) {
            __syncthreads();
            #pragma unroll
            for (int i=0;i<16;i++) { int f=t+i*256; int k=f>>7, o=f&127; As[k][o] = w2[o*64 + kc + k]; }
            #pragma unroll
            for (int i=0;i<16;i++) { int f=t+i*256; int k=f>>7, n=f&127;
                Bs[k][n] = g_h1[(b*64 + kc + k)*2048 + n0 + n]; }
            __syncthreads();
            #pragma unroll
            for (int k=0;k<32;k++) {
                float a[8], bb[8];
                *(float4*)&a[0]  = *(const float4*)&As[k][ty*8];
                *(float4*)&a[4]  = *(const float4*)&As[k][ty*8+4];
                *(float4*)&bb[0] = *(const float4*)&Bs[k][tx*8];
                *(float4*)&bb[4] = *(const float4*)&Bs[k][tx*8+4];
                #pragma unroll
                for (int r=0;r<8;r++)
                    #pragma unroll
                    for (int c=0;c<8;c++) acc[r][c] = fmaf(a[r], bb[c], acc[r][c]);
            }
        }
        #pragma unroll
        for (int r=0;r<8;r++) {
            int o = ty*8 + r;
            float bias = b2[o];
            float rs = 0.f, rq = 0.f;
            float v[8];
            #pragma unroll
            for (int c=0;c<8;c++) { v[c] = acc[r][c] + bias; rs += v[c]; rq = fmaf(v[c], v[c], rq); }
            float* dst = &g_h2[(b*128+o)*2048 + n0 + tx*8];
            *(float4*)dst     = *(float4*)&v[0];
            *(float4*)(dst+4) = *(float4*)&v[4];
            atomicAdd(&s_sum[o], rs);
            atomicAdd(&s_ss[o], rq);
        }
        __syncthreads();
        if (t < 128) { atomicAdd(&g_c2sum[t], s_sum[t]); atomicAdd(&g_c2ss[t], s_ss[t]); }
    }
    gsync(64);

    {
        float (*smv)[65] = (float(*)[65])sbuf;
        float* ssc = sbuf + 8320;
        float* ssh = sbuf + 8448;
        if (t < 128) {
            float mean = g_c2sum[t] * (1.f/8192.f);
            float var = g_c2ss[t] * (1.f/8192.f) - mean*mean;
            float sc = g2[t]*rsqrtf(var + BEPS);
            ssc[t] = sc;
            ssh[t] = be2[t] - mean*sc;
        }
        __syncthreads();
        #pragma unroll
        for (int inst_i = 0; inst_i < 2; inst_i++) {
            int inst = blk*2 + inst_i;
            int b = inst >> 5, n0 = (inst & 31)*64;
            #pragma unroll
            for (int i=0;i<32;i++) {
                int f = t + i*256; int c = f >> 6, n = f & 63;
                float v = g_h2[(b*128+c)*2048 + n0 + n];
                smv[c][n] = fmaxf(fmaf(ssc[c], v, ssh[c]), 0.f);
            }
            __syncthreads();
            int col = t & 63, q = t >> 6;
            __half* dst = g_Bs + (size_t)(b*2048 + n0 + col)*128;
            #pragma unroll
            for (int ch=0; ch<32; ch++)
                dst[q*32+ch] = __float2half_rn(smv[q*32+ch][col]);
            __syncthreads();
        }
    }
}

// ---------------- caps GEMM via mma.sync fp16: D = A · B^T, K=128 --------------
#define LDAH 136
#define A_BYTES (128*LDAH*2)
#define CAPS_SMEM (2*A_BYTES)

__global__ void __launch_bounds__(256,2) k_caps_mma() {
    extern __shared__ char sm[];
    const uint32_t sb = smem_u32(sm);
    const int t = threadIdx.x, w = t >> 5, lane = t & 31;
    const int row0 = blockIdx.y * 128, col0 = blockIdx.x * 128;
    const int wm = (w >> 1) * 32, wn = (w & 1) * 64;
    const int lr = lane & 7, mi = lane >> 3;

    const uint32_t aoff = ((uint32_t)(wm + (mi&1)*8 + lr)*LDAH + (mi>>1)*8) * 2;
    const uint32_t boff = ((uint32_t)(wn + (mi>>1)*8 + lr)*LDAH + (mi&1)*8) * 2;

    #pragma unroll
    for (int i=0;i<8;i++) {
        int idx = t + i*256; int r = idx >> 4, j = idx & 15;
        cp16(sb + (uint32_t)(r*LDAH)*2 + j*16,
             g_Ah + (size_t)(row0 + r)*128 + j*8);
    }
    #pragma unroll
    for (int i=0;i<8;i++) {
        int idx = t + i*256; int r = idx >> 4, j = idx & 15;
        cp16(sb + A_BYTES + (uint32_t)(r*LDAH)*2 + j*16,
             g_Bs + (size_t)(col0 + r)*128 + j*8);
    }
    CP_COMMIT();

    float acc[2][8][4];
    #pragma unroll
    for (int mt=0;mt<2;mt++)
        #pragma unroll
        for (int nt=0;nt<8;nt++)
            #pragma unroll
            for (int e=0;e<4;e++) acc[mt][nt][e] = 0.f;

    CP_WAIT(0);
    __syncthreads();

    #pragma unroll
    for (int ks=0; ks<8; ks++) {
        uint32_t a[2][4];
        #pragma unroll
        for (int mt=0;mt<2;mt++)
            ldsm4(a[mt], sb + aoff + (uint32_t)(mt*16*LDAH)*2 + ks*32);
        #pragma unroll
        for (int ntp=0;ntp<4;ntp++) {
            uint32_t b[4];
            ldsm4(b, sb + A_BYTES + boff + (uint32_t)(ntp*16*LDAH)*2 + ks*32);
            #pragma unroll
            for (int mt=0;mt<2;mt++) {
                mma16816(acc[mt][ntp*2],   a[mt], b);
                mma16816(acc[mt][ntp*2+1], a[mt], b+2);
            }
        }
    }
    __syncthreads();

    float4* cmb = (float4*)sm;
    #pragma unroll
    for (int mt=0;mt<2;mt++) {
        float s0=0.f,q0=0.f,mx0=-3.4028235e38f,mn0=3.4028235e38f;
        float s1=0.f,q1=0.f,mx1=-3.4028235e38f,mn1=3.4028235e38f;
        #pragma unroll
        for (int nt=0;nt<8;nt++) {
            float d0=acc[mt][nt][0], d1=acc[mt][nt][1];
            float d2=acc[mt][nt][2], d3=acc[mt][nt][3];
            s0 += d0+d1; q0 = fmaf(d0,d0,fmaf(d1,d1,q0));
            mx0 = fmaxf(mx0, fmaxf(d0,d1)); mn0 = fminf(mn0, fminf(d0,d1));
            s1 += d2+d3; q1 = fmaf(d2,d2,fmaf(d3,d3,q1));
            mx1 = fmaxf(mx1, fmaxf(d2,d3)); mn1 = fminf(mn1, fminf(d2,d3));
        }
        #pragma unroll
        for (int o=1;o<4;o<<=1) {
            s0 += __shfl_xor_sync(0xffffffffu, s0, o);
            q0 += __shfl_xor_sync(0xffffffffu, q0, o);
            mx0 = fmaxf(mx0, __shfl_xor_sync(0xffffffffu, mx0, o));
            mn0 = fminf(mn0, __shfl_xor_sync(0xffffffffu, mn0, o));
            s1 += __shfl_xor_sync(0xffffffffu, s1, o);
            q1 += __shfl_xor_sync(0xffffffffu, q1, o);
            mx1 = fmaxf(mx1, __shfl_xor_sync(0xffffffffu, mx1, o));
            mn1 = fminf(mn1, __shfl_xor_sync(0xffffffffu, mn1, o));
        }
        if ((lane & 3) == 0) {
            int r0 = wm + mt*16 + (lane >> 2);
            cmb[r0*2 + (w&1)]     = make_float4(s0, q0, mx0, mn0);
            cmb[(r0+8)*2 + (w&1)] = make_float4(s1, q1, mx1, mn1);
        }
    }
    __syncthreads();
    if (t < 128) {
        float4 a = cmb[t*2+0], b = cmb[t*2+1];
        int gi = (row0 + t)*64 + blockIdx.x;
        g_psum[gi] = a.x+b.x;
        g_pss[gi]  = a.y+b.y;
        g_pmx[gi]  = fmaxf(a.z,b.z);
        g_pmn[gi]  = fminf(a.w,b.w);
    }
}

// ---------------- redstats + ufin, 256 blocks (65536 threads) ----------------
__global__ void __launch_bounds__(256) k_redufin(const float* __restrict__ b3,
        const float* __restrict__ g3, const float* __restrict__ be3) {
    int bid = blockIdx.x, t = threadIdx.x;
    int gid = bid*256 + t;
    // ---- redstats: 4 threads per row; thread qt owns nt [qt*16, qt*16+16) = batch qt
    {
        int row = gid >> 2, qt = gid & 3;
        float s = 0.f, q = 0.f;
        float mx = -3.4028235e38f, mn = 3.4028235e38f;
        int base = row*64 + qt*16;
        #pragma unroll
        for (int i=0;i<16;i++) {
            s += g_psum[base+i]; q += g_pss[base+i];
            mx = fmaxf(mx, g_pmx[base+i]);
            mn = fminf(mn, g_pmn[base+i]);
        }
        #pragma unroll
        for (int o=1;o<4;o<<=1) {
            s += __shfl_xor_sync(0xffffffffu, s, o);
            q += __shfl_xor_sync(0xffffffffu, q, o);
        }
        float bias = b3[row];
        float* o = g_rowstats + row*10;
        o[2+qt] = mx + bias;
        o[6+qt] = mn + bias;
        if (qt == 0) {
            float sv = s + 8192.f*bias;
            float qv = q + 2.f*bias*s + 8192.f*bias*bias;
            o[0] = sv; o[1] = qv;
        }
    }
    gsync(256);
    // ---- ufin: 16 threads per (b,p), one q each ----
    {
        int idx = gid >> 4;               // 4096 (b,p)
        int q = t & 15;
        int b = idx >> 10, p = idx & 1023;
        int row = q*1024 + p;
        const float* st = g_rowstats + row*10;
        float mean = st[0]*(1.f/8192.f);
        float var  = st[1]*(1.f/8192.f) - mean*mean;
        float sc = g3[row]*rsqrtf(var + BEPS);
        float m = (sc >= 0.f) ? st[2+b] : st[6+b];
        float v = fmaf(sc, m - mean, be3[row]);
        float sn = v*v;
        #pragma unroll
        for (int o=1;o<16;o<<=1) sn += __shfl_xor_sync(0xffffffffu, sn, o);
        float coef = sn/((1.f+sn)*sqrtf(sn));
        g_u[(b*1024+p)*16 + q] = coef*v;
    }
}

// ---------------- u_hat = einsum(lpvq,bpq->blpv), fp16, big grid ----------------
__global__ void __launch_bounds__(256) k_uhat(const float* __restrict__ Wr) {
    int gid = blockIdx.x*256 + threadIdx.x;   // 262144
    int lp = gid >> 2, vg = gid & 3;
    int l = lp >> 10, p = lp & 1023;
    float u0[16], u1[16], u2[16], u3[16];
    #pragma unroll
    for (int j=0;j<4;j++) {
        *(float4*)&u0[j*4] = *(const float4*)&g_u[(0*1024+p)*16 + j*4];
        *(float4*)&u1[j*4] = *(const float4*)&g_u[(1*1024+p)*16 + j*4];
        *(float4*)&u2[j*4] = *(const float4*)&g_u[(2*1024+p)*16 + j*4];
        *(float4*)&u3[j*4] = *(const float4*)&g_u[(3*1024+p)*16 + j*4];
    }
    const float4* wr = (const float4*)(Wr + (size_t)lp*1024 + vg*256);
    size_t obase = (((size_t)l*1024 + p)*64 + vg*16) >> 3;   // uint4 units
    uint4* o0 = (uint4*)g_uhat_h + obase;
    uint4* o1 = (uint4*)g_uhat_h + ((size_t)64*1024*64 >> 3) + obase;
    uint4* o2 = (uint4*)g_uhat_h + ((size_t)2*64*1024*64 >> 3) + obase;
    uint4* o3 = (uint4*)g_uhat_h + ((size_t)3*64*1024*64 >> 3) + obase;
    #pragma unroll
    for (int vc = 0; vc < 2; vc++) {          // 8 v per chunk
        uint32_t pk0[4], pk1[4], pk2[4], pk3[4];
        #pragma unroll
        for (int v2 = 0; v2 < 4; v2++) {
            float da[4], db[4];
            #pragma unroll
            for (int h = 0; h < 2; h++) {
                int v = vc*8 + v2*2 + h;
                float wv[16];
                *(float4*)&wv[0]  = wr[v*4+0];
                *(float4*)&wv[4]  = wr[v*4+1];
                *(float4*)&wv[8]  = wr[v*4+2];
                *(float4*)&wv[12] = wr[v*4+3];
                float d0=0.f, d1=0.f, d2=0.f, d3=0.f;
                #pragma unroll
                for (int q=0;q<16;q++) {
                    d0 = fmaf(wv[q], u0[q], d0);
                    d1 = fmaf(wv[q], u1[q], d1);
                    d2 = fmaf(wv[q], u2[q], d2);
                    d3 = fmaf(wv[q], u3[q], d3);
                }
                if (h == 0) { da[0]=d0; da[1]=d1; da[2]=d2; da[3]=d3; }
                else        { db[0]=d0; db[1]=d1; db[2]=d2; db[3]=d3; }
            }
            __half2 h0 = __floats2half2_rn(da[0], db[0]);
            __half2 h1 = __floats2half2_rn(da[1], db[1]);
            __half2 h2 = __floats2half2_rn(da[2], db[2]);
            __half2 h3 = __floats2half2_rn(da[3], db[3]);
            pk0[v2] = *(uint32_t*)&h0; pk1[v2] = *(uint32_t*)&h1;
            pk2[v2] = *(uint32_t*)&h2; pk3[v2] = *(uint32_t*)&h3;
        }
        o0[vc] = make_uint4(pk0[0],pk0[1],pk0[2],pk0[3]);
        o1[vc] = make_uint4(pk1[0],pk1[1],pk1[2],pk1[3]);
        o2[vc] = make_uint4(pk2[0],pk2[1],pk2[2],pk2[3]);
        o3[vc] = make_uint4(pk3[0],pk3[1],pk3[2],pk3[3]);
    }
}

// ---------------- persistent routing + heads ----------------
__global__ void __launch_bounds__(256) k_route(const float* __restrict__ fcw,
        const float* __restrict__ fcb, float* __restrict__ out) {
    int bid = blockIdx.x, t = threadIdx.x;
    __shared__ float cs[1024];
    __shared__ float red[8][64];
    __shared__ float sq[64];
    __shared__ float s_coef;
    __shared__ float vs[64];

    int b = bid >> 6, l = bid & 63;
    const __half2* uh = (const __half2*)(g_uhat_h + ((long)(b*64+l))*65536);
    float* bp = g_bij + (b*64+l)*1024;

    for (int it = 0; it < 3; it++) {
        {
            int item = bid*16 + (t >> 4);
            int sub = t & 15;
            int bb = item >> 10, pp = item & 1023;
            const float* bcol = g_bij + bb*65536 + pp;
            float v0 = bcol[(sub*4+0)*1024];
            float v1 = bcol[(sub*4+1)*1024];
            float v2 = bcol[(sub*4+2)*1024];
            float v3 = bcol[(sub*4+3)*1024];
            float mx = fmaxf(fmaxf(v0,v1), fmaxf(v2,v3));
            #pragma unroll
            for (int o=8;o>0;o>>=1) mx = fmaxf(mx, __shfl_down_sync(0xffffffffu, mx, o, 16));
            mx = __shfl_sync(0xffffffffu, mx, 0, 16);
            float s = __expf(v0-mx)+__expf(v1-mx)+__expf(v2-mx)+__expf(v3-mx);
            #pragma unroll
            for (int o=8;o>0;o>>=1) s += __shfl_down_sync(0xffffffffu, s, o, 16);
            if (sub == 0) { g_norm[item*2] = mx; g_norm[item*2+1] = 1.f/s; }
        }
        gsync(256);

        {
            int j = t & 31, pc = t >> 5;
            for (int i=t;i<1024;i+=256) {
                float bv = bp[i];
                float mx = g_norm[(b*1024+i)*2], inv = g_norm[(b*1024+i)*2+1];
                cs[i] = __expf(bv - mx) * inv;
            }
            __syncthreads();
            float2 a0 = {0.f,0.f}, a1 = {0.f,0.f};
            int pb = pc*128;
            #pragma unroll 4
            for (int p = pb; p < pb+128; p += 2) {
                float2 h0 = __half22float2(uh[p*32 + j]);
                float2 h1 = __half22float2(uh[(p+1)*32 + j]);
                float c0 = cs[p], c1 = cs[p+1];
                a0.x = fmaf(c0, h0.x, a0.x); a0.y = fmaf(c0, h0.y, a0.y);
                a1.x = fmaf(c1, h1.x, a1.x); a1.y = fmaf(c1, h1.y, a1.y);
            }
            red[pc][2*j]   = a0.x + a1.x;
            red[pc][2*j+1] = a0.y + a1.y;
            __syncthreads();
            if (t < 64) {
                float vr = 0.f;
                #pragma unroll
                for (int k=0;k<8;k++) vr += red[k][t];
                red[0][t] = vr;
                sq[t] = vr*vr;
            }
            __syncthreads();
            if (t == 0) {
                float sn = 0.f;
                for (int i=0;i<64;i++) sn += sq[i];
                s_coef = sn/((1.f+sn)*sqrtf(sn));
            }
            __syncthreads();
            if (t < 64) {
                float vv = s_coef*red[0][t];
                vs[t] = vv;
                if (it == 2) g_vj[(b*64+l)*64 + t] = vv;
            }
            __syncthreads();
        }
        if (it < 2) {
            #pragma unroll
            for (int p4 = 0; p4 < 4; p4++) {
                int p = t*4 + p4;
                const __half2* row = uh + p*32;
                float a = 0.f;
                #pragma unroll 8
                for (int j = 0; j < 32; j++) {
                    float2 h = __half22float2(row[j]);
                    a = fmaf(vs[2*j], h.x, fmaf(vs[2*j+1], h.y, a));
                }
                bp[p] += a;
            }
        }
        gsync(256);
    }

    if (bid < 160) {
        int bo = bid/40, o = bid%40;
        const float* vj = g_vj + bo*4096;
        const float* wr = fcw + o*4096;
        float acc = 0.f;
        for (int i=t;i<4096;i+=256) acc = fmaf(vj[i], wr[i], acc);
        #pragma unroll
        for (int off=16;off>0;off>>=1) acc += __shfl_down_sync(0xffffffffu, acc, off);
        if ((t&31)==0) sq[t>>5] = acc;
        __syncthreads();
        if (t==0) {
            float r = 0.f;
            #pragma unroll
            for (int k=0;k<8;k++) r += sq[k];
            out[bo*40+o] = r + fcb[o];
        }
    } else if (bid < 224) {
        int w = t >> 5, lane = t & 31;
        int item = (bid-160)*4 + (w >> 1), half = w & 1;
        float v = g_vj[item*64 + half*32 + lane];
        float sv = v*v;
        #pragma unroll
        for (int off=16;off>0;off>>=1) sv += __shfl_down_sync(0xffffffffu, sv, off);
        if (lane==0) red[0][w] = sv;
        __syncthreads();
        if (t < 4) out[160 + (bid-160)*4 + t] = sqrtf(red[0][2*t] + red[0][2*t+1]);
    }
}

// ---------------- launch ----------------
extern "C" void kernel_launch(void* const* d_in, const int* in_sizes, int n_in,
                              void* d_out, int out_size) {
    const float* x   = (const float*)d_in[0];
    const float* w1  = (const float*)d_in[1];
    const float* b1  = (const float*)d_in[2];
    const float* g1  = (const float*)d_in[3];
    const float* be1 = (const float*)d_in[4];
    const float* w2  = (const float*)d_in[5];
    const float* b2  = (const float*)d_in[6];
    const float* g2  = (const float*)d_in[7];
    const float* be2 = (const float*)d_in[8];
    const float* w3  = (const float*)d_in[9];
    const float* b3  = (const float*)d_in[10];
    const float* g3  = (const float*)d_in[11];
    const float* be3 = (const float*)d_in[12];
    const float* Wr  = (const float*)d_in[13];
    const float* fcw = (const float*)d_in[14];
    const float* fcb = (const float*)d_in[15];
    float* out = (float*)d_out;

    cudaFuncSetAttribute(k_caps_mma, cudaFuncAttributeMaxDynamicSharedMemorySize, CAPS_SMEM);

    k_front<<<2433,256>>>(x,w1,b1,g1,be1,w3);          // launch 0
    k_conv2sb<<<64,256>>>(w2,b2,g2,be2);               // launch 1
    k_caps_mma<<<dim3(64,128),256,CAPS_SMEM>>>();      // launch 2
    k_redufin<<<256,256>>>(b3,g3,be3);                 // launch 3  <- profiled
    k_uhat<<<1024,256>>>(Wr);                          // launch 4
    k_route<<<256,256>>>(fcw,fcb,out);                 // launch 5
}

// round 16
// speedup vs baseline: 1.1697x; 1.0992x over previous
#include <cuda_runtime.h>
#include <cuda_fp16.h>
#include <cstdint>
#include <math.h>

#define BEPS 1e-5f

// ---------------- scratch (static device globals; no allocation) ----------------
__device__ float g_h1[4*64*2048];
__device__ float g_h2[4*128*2048];
__device__ float g_c2sum[128], g_c2ss[128];
__device__ __align__(16) __half g_Ah[16384*128];
__device__ __align__(16) __half g_Bs[8192*128];
__device__ __align__(16) float4 g_pstat[16384*64];   // per (row, ntile): s,q,mx,mn
__device__ float g_rowstats[16384*10];
__device__ float g_u[4*1024*16];
__device__ __align__(16) __half g_uhat_h[(long)4*64*1024*64]; // 33.5MB [b][l][p][v]
__device__ float g_bij[4*64*1024];
__device__ float g_norm[4096*2];
__device__ float g_vj[4*64*64];
__device__ unsigned int g_cnt = 0;
__device__ volatile unsigned int g_gen = 0;

__device__ __forceinline__ uint32_t smem_u32(const void* p) {
    uint32_t a;
    asm("{ .reg .u64 t; cvta.to.shared.u64 t, %1; cvt.u32.u64 %0, t; }" : "=r"(a) : "l"(p));
    return a;
}
__device__ __forceinline__ void cp16(uint32_t dst, const void* src) {
    asm volatile("cp.async.cg.shared.global [%0], [%1], 16;" :: "r"(dst), "l"(src));
}
#define CP_COMMIT() asm volatile("cp.async.commit_group;" ::: "memory")
#define CP_WAIT(n)  asm volatile("cp.async.wait_group %0;" :: "n"(n) : "memory")

__device__ __forceinline__ void ldsm4(uint32_t* r, uint32_t addr) {
    asm volatile("ldmatrix.sync.aligned.m8n8.x4.shared.b16 {%0,%1,%2,%3}, [%4];"
        : "=r"(r[0]), "=r"(r[1]), "=r"(r[2]), "=r"(r[3]) : "r"(addr));
}
__device__ __forceinline__ void mma16816(float* d, const uint32_t* a, const uint32_t* b) {
    asm volatile("mma.sync.aligned.m16n8k16.row.col.f32.f16.f16.f32 "
        "{%0,%1,%2,%3}, {%4,%5,%6,%7}, {%8,%9}, {%0,%1,%2,%3};"
        : "+f"(d[0]), "+f"(d[1]), "+f"(d[2]), "+f"(d[3])
        : "r"(a[0]), "r"(a[1]), "r"(a[2]), "r"(a[3]), "r"(b[0]), "r"(b[1]));
}

// grid-wide barrier (all nb blocks co-resident; deterministic)
__device__ __forceinline__ void gsync(unsigned int nb) {
    __threadfence();
    __syncthreads();
    if (threadIdx.x == 0) {
        unsigned int my = g_gen;
        if (atomicAdd(&g_cnt, 1u) == nb - 1u) {
            g_cnt = 0;
            __threadfence();
            g_gen = my + 1u;
        } else {
            while (g_gen == my) { }
        }
    }
    __syncthreads();
}

// ---------------- front: conv1(+inline bn1) | cast w3 | zero c2 ----------
__global__ void __launch_bounds__(256) k_front(const float* __restrict__ x,
        const float* __restrict__ w1, const float* __restrict__ b1,
        const float* __restrict__ g1, const float* __restrict__ be1,
        const float* __restrict__ w3) {
    int blk = blockIdx.x, t = threadIdx.x;
    if (blk < 128) {
        int nb = blk & 7, b = (blk >> 3) & 3, og = (blk >> 5) * 16;
        __shared__ float red[9][8];
        __shared__ float m[3], cov[3][3];
        __shared__ float ssc[16], ssh[16];
        float s0=0,s1=0,s2=0,p00=0,p01=0,p02=0,p11=0,p12=0,p22=0;
        for (int i = t; i < 8192; i += 256) {
            int bb = i >> 11, n = i & 2047;
            const float* xb = x + bb*3*2048 + n;
            float a = xb[0], c = xb[2048], d = xb[4096];
            s0+=a; s1+=c; s2+=d;
            p00+=a*a; p01+=a*c; p02+=a*d; p11+=c*c; p12+=c*d; p22+=d*d;
        }
        float vals[9] = {s0,s1,s2,p00,p01,p02,p11,p12,p22};
        int lane = t & 31, w = t >> 5;
        #pragma unroll
        for (int j=0;j<9;j++) {
            float v = vals[j];
            #pragma unroll
            for (int o=16;o>0;o>>=1) v += __shfl_down_sync(0xffffffffu, v, o);
            if (lane==0) red[j][w] = v;
        }
        __syncthreads();
        if (t < 9) {
            float v = 0;
            for (int ww=0; ww<8; ww++) v += red[t][ww];
            red[t][0] = v * (1.f/8192.f);
        }
        __syncthreads();
        if (t == 0) {
            m[0]=red[0][0]; m[1]=red[1][0]; m[2]=red[2][0];
            cov[0][0]=red[3][0]-m[0]*m[0];
            cov[0][1]=cov[1][0]=red[4][0]-m[0]*m[1];
            cov[0][2]=cov[2][0]=red[5][0]-m[0]*m[2];
            cov[1][1]=red[6][0]-m[1]*m[1];
            cov[1][2]=cov[2][1]=red[7][0]-m[1]*m[2];
            cov[2][2]=red[8][0]-m[2]*m[2];
        }
        __syncthreads();
        if (t < 16) {
            int o = og + t;
            float wv0=w1[o*3], wv1=w1[o*3+1], wv2=w1[o*3+2];
            float mean = wv0*m[0]+wv1*m[1]+wv2*m[2] + b1[o];
            float var = wv0*wv0*cov[0][0] + wv1*wv1*cov[1][1] + wv2*wv2*cov[2][2]
                      + 2.f*(wv0*wv1*cov[0][1] + wv0*wv2*cov[0][2] + wv1*wv2*cov[1][2]);
            float sc = g1[o]*rsqrtf(var + BEPS);
            ssc[t] = sc;
            ssh[t] = be1[o] - mean*sc;
        }
        __syncthreads();
        int n = nb*256 + t;
        float x0 = x[b*6144 + n], x1 = x[b*6144 + 2048 + n], x2 = x[b*6144 + 4096 + n];
        #pragma unroll
        for (int oo=0;oo<16;oo++) {
            int o = og + oo;
            float pre = fmaf(w1[o*3], x0, fmaf(w1[o*3+1], x1, fmaf(w1[o*3+2], x2, b1[o])));
            float h = fmaf(ssc[oo], pre, ssh[oo]);
            g_h1[(b*64+o)*2048 + n] = fmaxf(h, 0.f);
        }
    } else if (blk < 2176) {
        int blk2 = blk - 128;
        #pragma unroll
        for (int i=0;i<4;i++) {
            int id = blk2*1024 + i*256 + t;
            g_Ah[id] = __float2half_rn(w3[id]);
        }
    } else {
        if (t < 128) { g_c2sum[t] = 0.f; g_c2ss[t] = 0.f; }
    }
}

// ---------------- conv2 + BN2 + relu + transpose -> B fp16, one persistent kernel
__global__ void __launch_bounds__(256) k_conv2sb(const float* __restrict__ w2,
        const float* __restrict__ b2, const float* __restrict__ g2,
        const float* __restrict__ be2) {
    __shared__ float sbuf[8576];
    int blk = blockIdx.x, t = threadIdx.x;

    {
        float (*As)[128] = (float(*)[128])sbuf;
        float (*Bs)[128] = (float(*)[128])(sbuf + 4096);
        float* s_sum = sbuf + 8192;
        float* s_ss  = sbuf + 8320;
        int b = blk >> 4, n0 = (blk & 15)*128;
        int tx = t & 15, ty = t >> 4;
        float acc[8][8];
        #pragma unroll
        for (int r=0;r<8;r++)
            #pragma unroll
            for (int c=0;c<8;c++) acc[r][c] = 0.f;
        if (t < 128) { s_sum[t] = 0.f; s_ss[t] = 0.f; }
        for (int kc = 0; kc < 64; kc += 32) {
            __syncthreads();
            #pragma unroll
            for (int i=0;i<16;i++) { int f=t+i*256; int k=f>>7, o=f&127; As[k][o] = w2[o*64 + kc + k]; }
            #pragma unroll
            for (int i=0;i<16;i++) { int f=t+i*256; int k=f>>7, n=f&127;
                Bs[k][n] = g_h1[(b*64 + kc + k)*2048 + n0 + n]; }
            __syncthreads();
            #pragma unroll
            for (int k=0;k<32;k++) {
                float a[8], bb[8];
                *(float4*)&a[0]  = *(const float4*)&As[k][ty*8];
                *(float4*)&a[4]  = *(const float4*)&As[k][ty*8+4];
                *(float4*)&bb[0] = *(const float4*)&Bs[k][tx*8];
                *(float4*)&bb[4] = *(const float4*)&Bs[k][tx*8+4];
                #pragma unroll
                for (int r=0;r<8;r++)
                    #pragma unroll
                    for (int c=0;c<8;c++) acc[r][c] = fmaf(a[r], bb[c], acc[r][c]);
            }
        }
        #pragma unroll
        for (int r=0;r<8;r++) {
            int o = ty*8 + r;
            float bias = b2[o];
            float rs = 0.f, rq = 0.f;
            float v[8];
            #pragma unroll
            for (int c=0;c<8;c++) { v[c] = acc[r][c] + bias; rs += v[c]; rq = fmaf(v[c], v[c], rq); }
            float* dst = &g_h2[(b*128+o)*2048 + n0 + tx*8];
            *(float4*)dst     = *(float4*)&v[0];
            *(float4*)(dst+4) = *(float4*)&v[4];
            atomicAdd(&s_sum[o], rs);
            atomicAdd(&s_ss[o], rq);
        }
        __syncthreads();
        if (t < 128) { atomicAdd(&g_c2sum[t], s_sum[t]); atomicAdd(&g_c2ss[t], s_ss[t]); }
    }
    gsync(64);

    {
        float (*smv)[65] = (float(*)[65])sbuf;
        float* ssc = sbuf + 8320;
        float* ssh = sbuf + 8448;
        if (t < 128) {
            float mean = g_c2sum[t] * (1.f/8192.f);
            float var = g_c2ss[t] * (1.f/8192.f) - mean*mean;
            float sc = g2[t]*rsqrtf(var + BEPS);
            ssc[t] = sc;
            ssh[t] = be2[t] - mean*sc;
        }
        __syncthreads();
        #pragma unroll
        for (int inst_i = 0; inst_i < 2; inst_i++) {
            int inst = blk*2 + inst_i;
            int b = inst >> 5, n0 = (inst & 31)*64;
            #pragma unroll
            for (int i=0;i<32;i++) {
                int f = t + i*256; int c = f >> 6, n = f & 63;
                float v = g_h2[(b*128+c)*2048 + n0 + n];
                smv[c][n] = fmaxf(fmaf(ssc[c], v, ssh[c]), 0.f);
            }
            __syncthreads();
            int col = t & 63, q = t >> 6;
            __half* dst = g_Bs + (size_t)(b*2048 + n0 + col)*128;
            #pragma unroll
            for (int ch=0; ch<32; ch++)
                dst[q*32+ch] = __float2half_rn(smv[q*32+ch][col]);
            __syncthreads();
        }
    }
}

// ---------------- caps GEMM via mma.sync fp16: D = A · B^T, K=128 --------------
#define LDAH 136
#define A_BYTES (128*LDAH*2)
#define CAPS_SMEM (2*A_BYTES)

__global__ void __launch_bounds__(256,2) k_caps_mma() {
    extern __shared__ char sm[];
    const uint32_t sb = smem_u32(sm);
    const int t = threadIdx.x, w = t >> 5, lane = t & 31;
    const int row0 = blockIdx.y * 128, col0 = blockIdx.x * 128;
    const int wm = (w >> 1) * 32, wn = (w & 1) * 64;
    const int lr = lane & 7, mi = lane >> 3;

    const uint32_t aoff = ((uint32_t)(wm + (mi&1)*8 + lr)*LDAH + (mi>>1)*8) * 2;
    const uint32_t boff = ((uint32_t)(wn + (mi>>1)*8 + lr)*LDAH + (mi&1)*8) * 2;

    #pragma unroll
    for (int i=0;i<8;i++) {
        int idx = t + i*256; int r = idx >> 4, j = idx & 15;
        cp16(sb + (uint32_t)(r*LDAH)*2 + j*16,
             g_Ah + (size_t)(row0 + r)*128 + j*8);
    }
    #pragma unroll
    for (int i=0;i<8;i++) {
        int idx = t + i*256; int r = idx >> 4, j = idx & 15;
        cp16(sb + A_BYTES + (uint32_t)(r*LDAH)*2 + j*16,
             g_Bs + (size_t)(col0 + r)*128 + j*8);
    }
    CP_COMMIT();

    float acc[2][8][4];
    #pragma unroll
    for (int mt=0;mt<2;mt++)
        #pragma unroll
        for (int nt=0;nt<8;nt++)
            #pragma unroll
            for (int e=0;e<4;e++) acc[mt][nt][e] = 0.f;

    CP_WAIT(0);
    __syncthreads();

    #pragma unroll
    for (int ks=0; ks<8; ks++) {
        uint32_t a[2][4];
        #pragma unroll
        for (int mt=0;mt<2;mt++)
            ldsm4(a[mt], sb + aoff + (uint32_t)(mt*16*LDAH)*2 + ks*32);
        #pragma unroll
        for (int ntp=0;ntp<4;ntp++) {
            uint32_t b[4];
            ldsm4(b, sb + A_BYTES + boff + (uint32_t)(ntp*16*LDAH)*2 + ks*32);
            #pragma unroll
            for (int mt=0;mt<2;mt++) {
                mma16816(acc[mt][ntp*2],   a[mt], b);
                mma16816(acc[mt][ntp*2+1], a[mt], b+2);
            }
        }
    }
    __syncthreads();

    float4* cmb = (float4*)sm;
    #pragma unroll
    for (int mt=0;mt<2;mt++) {
        float s0=0.f,q0=0.f,mx0=-3.4028235e38f,mn0=3.4028235e38f;
        float s1=0.f,q1=0.f,mx1=-3.4028235e38f,mn1=3.4028235e38f;
        #pragma unroll
        for (int nt=0;nt<8;nt++) {
            float d0=acc[mt][nt][0], d1=acc[mt][nt][1];
            float d2=acc[mt][nt][2], d3=acc[mt][nt][3];
            s0 += d0+d1; q0 = fmaf(d0,d0,fmaf(d1,d1,q0));
            mx0 = fmaxf(mx0, fmaxf(d0,d1)); mn0 = fminf(mn0, fminf(d0,d1));
            s1 += d2+d3; q1 = fmaf(d2,d2,fmaf(d3,d3,q1));
            mx1 = fmaxf(mx1, fmaxf(d2,d3)); mn1 = fminf(mn1, fminf(d2,d3));
        }
        #pragma unroll
        for (int o=1;o<4;o<<=1) {
            s0 += __shfl_xor_sync(0xffffffffu, s0, o);
            q0 += __shfl_xor_sync(0xffffffffu, q0, o);
            mx0 = fmaxf(mx0, __shfl_xor_sync(0xffffffffu, mx0, o));
            mn0 = fminf(mn0, __shfl_xor_sync(0xffffffffu, mn0, o));
            s1 += __shfl_xor_sync(0xffffffffu, s1, o);
            q1 += __shfl_xor_sync(0xffffffffu, q1, o);
            mx1 = fmaxf(mx1, __shfl_xor_sync(0xffffffffu, mx1, o));
            mn1 = fminf(mn1, __shfl_xor_sync(0xffffffffu, mn1, o));
        }
        if ((lane & 3) == 0) {
            int r0 = wm + mt*16 + (lane >> 2);
            cmb[r0*2 + (w&1)]     = make_float4(s0, q0, mx0, mn0);
            cmb[(r0+8)*2 + (w&1)] = make_float4(s1, q1, mx1, mn1);
        }
    }
    __syncthreads();
    if (t < 128) {
        float4 a = cmb[t*2+0], b = cmb[t*2+1];
        g_pstat[(row0 + t)*64 + blockIdx.x] =
            make_float4(a.x+b.x, a.y+b.y, fmaxf(a.z,b.z), fminf(a.w,b.w));
    }
}

// ---------------- redstats + ufin, 256 blocks (65536 threads) ----------------
__global__ void __launch_bounds__(256) k_redufin(const float* __restrict__ b3,
        const float* __restrict__ g3, const float* __restrict__ be3) {
    int bid = blockIdx.x, t = threadIdx.x;
    int gid = bid*256 + t;
    // ---- redstats: 4 threads per row; thread qt owns nt [qt*16, qt*16+16) = batch qt
    {
        int row = gid >> 2, qt = gid & 3;
        float s = 0.f, q = 0.f;
        float mx = -3.4028235e38f, mn = 3.4028235e38f;
        const float4* ps = g_pstat + row*64 + qt*16;
        #pragma unroll
        for (int i=0;i<16;i++) {
            float4 v = ps[i];
            s += v.x; q += v.y;
            mx = fmaxf(mx, v.z);
            mn = fminf(mn, v.w);
        }
        #pragma unroll
        for (int o=1;o<4;o<<=1) {
            s += __shfl_xor_sync(0xffffffffu, s, o);
            q += __shfl_xor_sync(0xffffffffu, q, o);
        }
        float bias = b3[row];
        float* o = g_rowstats + row*10;
        o[2+qt] = mx + bias;
        o[6+qt] = mn + bias;
        if (qt == 0) {
            float sv = s + 8192.f*bias;
            float qv = q + 2.f*bias*s + 8192.f*bias*bias;
            o[0] = sv; o[1] = qv;
        }
    }
    gsync(256);
    // ---- ufin: 16 threads per (b,p), one q each ----
    {
        int idx = gid >> 4;               // 4096 (b,p)
        int q = t & 15;
        int b = idx >> 10, p = idx & 1023;
        int row = q*1024 + p;
        const float* st = g_rowstats + row*10;
        float mean = st[0]*(1.f/8192.f);
        float var  = st[1]*(1.f/8192.f) - mean*mean;
        float sc = g3[row]*rsqrtf(var + BEPS);
        float m = (sc >= 0.f) ? st[2+b] : st[6+b];
        float v = fmaf(sc, m - mean, be3[row]);
        float sn = v*v;
        #pragma unroll
        for (int o=1;o<16;o<<=1) sn += __shfl_xor_sync(0xffffffffu, sn, o);
        float coef = sn/((1.f+sn)*sqrtf(sn));
        g_u[(b*1024+p)*16 + q] = coef*v;
    }
}

// ---------------- u_hat = einsum(lpvq,bpq->blpv), fp16, big grid ----------------
__global__ void __launch_bounds__(256) k_uhat(const float* __restrict__ Wr) {
    int gid = blockIdx.x*256 + threadIdx.x;   // 262144
    int lp = gid >> 2, vg = gid & 3;
    int l = lp >> 10, p = lp & 1023;
    float u0[16], u1[16], u2[16], u3[16];
    #pragma unroll
    for (int j=0;j<4;j++) {
        *(float4*)&u0[j*4] = *(const float4*)&g_u[(0*1024+p)*16 + j*4];
        *(float4*)&u1[j*4] = *(const float4*)&g_u[(1*1024+p)*16 + j*4];
        *(float4*)&u2[j*4] = *(const float4*)&g_u[(2*1024+p)*16 + j*4];
        *(float4*)&u3[j*4] = *(const float4*)&g_u[(3*1024+p)*16 + j*4];
    }
    const float4* wr = (const float4*)(Wr + (size_t)lp*1024 + vg*256);
    size_t obase = (((size_t)l*1024 + p)*64 + vg*16) >> 3;   // uint4 units
    uint4* o0 = (uint4*)g_uhat_h + obase;
    uint4* o1 = (uint4*)g_uhat_h + ((size_t)64*1024*64 >> 3) + obase;
    uint4* o2 = (uint4*)g_uhat_h + ((size_t)2*64*1024*64 >> 3) + obase;
    uint4* o3 = (uint4*)g_uhat_h + ((size_t)3*64*1024*64 >> 3) + obase;
    #pragma unroll
    for (int vc = 0; vc < 2; vc++) {          // 8 v per chunk
        uint32_t pk0[4], pk1[4], pk2[4], pk3[4];
        #pragma unroll
        for (int v2 = 0; v2 < 4; v2++) {
            float da[4], db[4];
            #pragma unroll
            for (int h = 0; h < 2; h++) {
                int v = vc*8 + v2*2 + h;
                float wv[16];
                *(float4*)&wv[0]  = wr[v*4+0];
                *(float4*)&wv[4]  = wr[v*4+1];
                *(float4*)&wv[8]  = wr[v*4+2];
                *(float4*)&wv[12] = wr[v*4+3];
                float d0=0.f, d1=0.f, d2=0.f, d3=0.f;
                #pragma unroll
                for (int q=0;q<16;q++) {
                    d0 = fmaf(wv[q], u0[q], d0);
                    d1 = fmaf(wv[q], u1[q], d1);
                    d2 = fmaf(wv[q], u2[q], d2);
                    d3 = fmaf(wv[q], u3[q], d3);
                }
                if (h == 0) { da[0]=d0; da[1]=d1; da[2]=d2; da[3]=d3; }
                else        { db[0]=d0; db[1]=d1; db[2]=d2; db[3]=d3; }
            }
            __half2 h0 = __floats2half2_rn(da[0], db[0]);
            __half2 h1 = __floats2half2_rn(da[1], db[1]);
            __half2 h2 = __floats2half2_rn(da[2], db[2]);
            __half2 h3 = __floats2half2_rn(da[3], db[3]);
            pk0[v2] = *(uint32_t*)&h0; pk1[v2] = *(uint32_t*)&h1;
            pk2[v2] = *(uint32_t*)&h2; pk3[v2] = *(uint32_t*)&h3;
        }
        o0[vc] = make_uint4(pk0[0],pk0[1],pk0[2],pk0[3]);
        o1[vc] = make_uint4(pk1[0],pk1[1],pk1[2],pk1[3]);
        o2[vc] = make_uint4(pk2[0],pk2[1],pk2[2],pk2[3]);
        o3[vc] = make_uint4(pk3[0],pk3[1],pk3[2],pk3[3]);
    }
}

// ---------------- persistent routing + heads ----------------
__global__ void __launch_bounds__(256) k_route(const float* __restrict__ fcw,
        const float* __restrict__ fcb, float* __restrict__ out) {
    int bid = blockIdx.x, t = threadIdx.x;
    __shared__ float cs[1024];
    __shared__ float red[8][64];
    __shared__ float sq[64];
    __shared__ float s_coef;
    __shared__ float vs[64];

    int b = bid >> 6, l = bid & 63;
    const __half2* uh = (const __half2*)(g_uhat_h + ((long)(b*64+l))*65536);
    float* bp = g_bij + (b*64+l)*1024;

    for (int it = 0; it < 3; it++) {
        // phase A: softmax normalizers (skipped for it=0: b_ij == 0 -> uniform)
        if (it > 0) {
            int item = bid*16 + (t >> 4);
            int sub = t & 15;
            int bb = item >> 10, pp = item & 1023;
            const float* bcol = g_bij + bb*65536 + pp;
            float v0 = bcol[(sub*4+0)*1024];
            float v1 = bcol[(sub*4+1)*1024];
            float v2 = bcol[(sub*4+2)*1024];
            float v3 = bcol[(sub*4+3)*1024];
            float mx = fmaxf(fmaxf(v0,v1), fmaxf(v2,v3));
            #pragma unroll
            for (int o=8;o>0;o>>=1) mx = fmaxf(mx, __shfl_down_sync(0xffffffffu, mx, o, 16));
            mx = __shfl_sync(0xffffffffu, mx, 0, 16);
            float s = __expf(v0-mx)+__expf(v1-mx)+__expf(v2-mx)+__expf(v3-mx);
            #pragma unroll
            for (int o=8;o>0;o>>=1) s += __shfl_down_sync(0xffffffffu, s, o, 16);
            if (sub == 0) { g_norm[item*2] = mx; g_norm[item*2+1] = 1.f/s; }
            gsync(256);
        }

        // phase B: v_j = squash(sum_p c*u_hat), c on the fly
        {
            int j = t & 31, pc = t >> 5;
            if (it == 0) {
                for (int i=t;i<1024;i+=256) cs[i] = 1.f/64.f;
            } else {
                for (int i=t;i<1024;i+=256) {
                    float bv = bp[i];
                    float mx = g_norm[(b*1024+i)*2], inv = g_norm[(b*1024+i)*2+1];
                    cs[i] = __expf(bv - mx) * inv;
                }
            }
            __syncthreads();
            float2 a0 = {0.f,0.f}, a1 = {0.f,0.f};
            int pb = pc*128;
            #pragma unroll 4
            for (int p = pb; p < pb+128; p += 2) {
                float2 h0 = __half22float2(uh[p*32 + j]);
                float2 h1 = __half22float2(uh[(p+1)*32 + j]);
                float c0 = cs[p], c1 = cs[p+1];
                a0.x = fmaf(c0, h0.x, a0.x); a0.y = fmaf(c0, h0.y, a0.y);
                a1.x = fmaf(c1, h1.x, a1.x); a1.y = fmaf(c1, h1.y, a1.y);
            }
            red[pc][2*j]   = a0.x + a1.x;
            red[pc][2*j+1] = a0.y + a1.y;
            __syncthreads();
            if (t < 64) {
                float vr = 0.f;
                #pragma unroll
                for (int k=0;k<8;k++) vr += red[k][t];
                red[0][t] = vr;
                sq[t] = vr*vr;
            }
            __syncthreads();
            if (t == 0) {
                float sn = 0.f;
                for (int i=0;i<64;i++) sn += sq[i];
                s_coef = sn/((1.f+sn)*sqrtf(sn));
            }
            __syncthreads();
            if (t < 64) {
                float vv = s_coef*red[0][t];
                vs[t] = vv;
                if (it == 2) g_vj[(b*64+l)*64 + t] = vv;
            }
            __syncthreads();
        }
        // fused b_ij update (iters 0,1); it=0 writes (b starts at 0, no init needed)
        if (it < 2) {
            #pragma unroll
            for (int p4 = 0; p4 < 4; p4++) {
                int p = t*4 + p4;
                const __half2* row = uh + p*32;
                float a = 0.f;
                #pragma unroll 8
                for (int j = 0; j < 32; j++) {
                    float2 h = __half22float2(row[j]);
                    a = fmaf(vs[2*j], h.x, fmaf(vs[2*j+1], h.y, a));
                }
                if (it == 0) bp[p] = a;
                else         bp[p] += a;
            }
        }
        gsync(256);
    }

    if (bid < 160) {
        int bo = bid/40, o = bid%40;
        const float* vj = g_vj + bo*4096;
        const float* wr = fcw + o*4096;
        float acc = 0.f;
        for (int i=t;i<4096;i+=256) acc = fmaf(vj[i], wr[i], acc);
        #pragma unroll
        for (int off=16;off>0;off>>=1) acc += __shfl_down_sync(0xffffffffu, acc, off);
        if ((t&31)==0) sq[t>>5] = acc;
        __syncthreads();
        if (t==0) {
            float r = 0.f;
            #pragma unroll
            for (int k=0;k<8;k++) r += sq[k];
            out[bo*40+o] = r + fcb[o];
        }
    } else if (bid < 224) {
        int w = t >> 5, lane = t & 31;
        int item = (bid-160)*4 + (w >> 1), half = w & 1;
        float v = g_vj[item*64 + half*32 + lane];
        float sv = v*v;
        #pragma unroll
        for (int off=16;off>0;off>>=1) sv += __shfl_down_sync(0xffffffffu, sv, off);
        if (lane==0) red[0][w] = sv;
        __syncthreads();
        if (t < 4) out[160 + (bid-160)*4 + t] = sqrtf(red[0][2*t] + red[0][2*t+1]);
    }
}

// ---------------- launch ----------------
extern "C" void kernel_launch(void* const* d_in, const int* in_sizes, int n_in,
                              void* d_out, int out_size) {
    const float* x   = (const float*)d_in[0];
    const float* w1  = (const float*)d_in[1];
    const float* b1  = (const float*)d_in[2];
    const float* g1  = (const float*)d_in[3];
    const float* be1 = (const float*)d_in[4];
    const float* w2  = (const float*)d_in[5];
    const float* b2  = (const float*)d_in[6];
    const float* g2  = (const float*)d_in[7];
    const float* be2 = (const float*)d_in[8];
    const float* w3  = (const float*)d_in[9];
    const float* b3  = (const float*)d_in[10];
    const float* g3  = (const float*)d_in[11];
    const float* be3 = (const float*)d_in[12];
    const float* Wr  = (const float*)d_in[13];
    const float* fcw = (const float*)d_in[14];
    const float* fcb = (const float*)d_in[15];
    float* out = (float*)d_out;

    cudaFuncSetAttribute(k_caps_mma, cudaFuncAttributeMaxDynamicSharedMemorySize, CAPS_SMEM);

    k_front<<<2177,256>>>(x,w1,b1,g1,be1,w3);          // launch 0
    k_conv2sb<<<64,256>>>(w2,b2,g2,be2);               // launch 1
    k_caps_mma<<<dim3(64,128),256,CAPS_SMEM>>>();      // launch 2
    k_redufin<<<256,256>>>(b3,g3,be3);                 // launch 3  <- profiled
    k_uhat<<<1024,256>>>(Wr);                          // launch 4
    k_route<<<256,256>>>(fcw,fcb,out);                 // launch 5
}

// round 17
// speedup vs baseline: 1.2568x; 1.0745x over previous
#include <cuda_runtime.h>
#include <cuda_fp16.h>
#include <cstdint>
#include <math.h>

#define BEPS 1e-5f

// ---------------- scratch (static device globals; no allocation) ----------------
__device__ float g_h1[4*64*2048];
__device__ float g_h2[4*128*2048];
__device__ float g_c2sum[128], g_c2ss[128];
__device__ __align__(16) __half g_Ah[16384*128];
__device__ __align__(16) __half g_Bs[8192*128];
__device__ __align__(16) float4 g_pstat[16384*64];   // per (row, ntile): s,q,mx,mn
__device__ float g_u[4*1024*16];
__device__ __align__(16) __half g_uhat_h[(long)4*64*1024*64]; // 33.5MB [b][l][p][v]
__device__ float g_bij[4*64*1024];
__device__ float g_norm[4096*2];
__device__ float g_vj[4*64*64];
__device__ unsigned int g_cnt = 0;
__device__ volatile unsigned int g_gen = 0;

__device__ __forceinline__ uint32_t smem_u32(const void* p) {
    uint32_t a;
    asm("{ .reg .u64 t; cvta.to.shared.u64 t, %1; cvt.u32.u64 %0, t; }" : "=r"(a) : "l"(p));
    return a;
}
__device__ __forceinline__ void cp16(uint32_t dst, const void* src) {
    asm volatile("cp.async.cg.shared.global [%0], [%1], 16;" :: "r"(dst), "l"(src));
}
#define CP_COMMIT() asm volatile("cp.async.commit_group;" ::: "memory")
#define CP_WAIT(n)  asm volatile("cp.async.wait_group %0;" :: "n"(n) : "memory")

__device__ __forceinline__ void ldsm4(uint32_t* r, uint32_t addr) {
    asm volatile("ldmatrix.sync.aligned.m8n8.x4.shared.b16 {%0,%1,%2,%3}, [%4];"
        : "=r"(r[0]), "=r"(r[1]), "=r"(r[2]), "=r"(r[3]) : "r"(addr));
}
__device__ __forceinline__ void mma16816(float* d, const uint32_t* a, const uint32_t* b) {
    asm volatile("mma.sync.aligned.m16n8k16.row.col.f32.f16.f16.f32 "
        "{%0,%1,%2,%3}, {%4,%5,%6,%7}, {%8,%9}, {%0,%1,%2,%3};"
        : "+f"(d[0]), "+f"(d[1]), "+f"(d[2]), "+f"(d[3])
        : "r"(a[0]), "r"(a[1]), "r"(a[2]), "r"(a[3]), "r"(b[0]), "r"(b[1]));
}

// grid-wide barrier (all nb blocks co-resident; deterministic)
__device__ __forceinline__ void gsync(unsigned int nb) {
    __threadfence();
    __syncthreads();
    if (threadIdx.x == 0) {
        unsigned int my = g_gen;
        if (atomicAdd(&g_cnt, 1u) == nb - 1u) {
            g_cnt = 0;
            __threadfence();
            g_gen = my + 1u;
        } else {
            while (g_gen == my) { }
        }
    }
    __syncthreads();
}

// ---------------- front: conv1(+inline bn1) | cast w3 | zero c2 ----------
__global__ void __launch_bounds__(256) k_front(const float* __restrict__ x,
        const float* __restrict__ w1, const float* __restrict__ b1,
        const float* __restrict__ g1, const float* __restrict__ be1,
        const float* __restrict__ w3) {
    int blk = blockIdx.x, t = threadIdx.x;
    if (blk < 128) {
        int nb = blk & 7, b = (blk >> 3) & 3, og = (blk >> 5) * 16;
        __shared__ float red[9][8];
        __shared__ float m[3], cov[3][3];
        __shared__ float ssc[16], ssh[16];
        float s0=0,s1=0,s2=0,p00=0,p01=0,p02=0,p11=0,p12=0,p22=0;
        for (int i = t; i < 8192; i += 256) {
            int bb = i >> 11, n = i & 2047;
            const float* xb = x + bb*3*2048 + n;
            float a = xb[0], c = xb[2048], d = xb[4096];
            s0+=a; s1+=c; s2+=d;
            p00+=a*a; p01+=a*c; p02+=a*d; p11+=c*c; p12+=c*d; p22+=d*d;
        }
        float vals[9] = {s0,s1,s2,p00,p01,p02,p11,p12,p22};
        int lane = t & 31, w = t >> 5;
        #pragma unroll
        for (int j=0;j<9;j++) {
            float v = vals[j];
            #pragma unroll
            for (int o=16;o>0;o>>=1) v += __shfl_down_sync(0xffffffffu, v, o);
            if (lane==0) red[j][w] = v;
        }
        __syncthreads();
        if (t < 9) {
            float v = 0;
            for (int ww=0; ww<8; ww++) v += red[t][ww];
            red[t][0] = v * (1.f/8192.f);
        }
        __syncthreads();
        if (t == 0) {
            m[0]=red[0][0]; m[1]=red[1][0]; m[2]=red[2][0];
            cov[0][0]=red[3][0]-m[0]*m[0];
            cov[0][1]=cov[1][0]=red[4][0]-m[0]*m[1];
            cov[0][2]=cov[2][0]=red[5][0]-m[0]*m[2];
            cov[1][1]=red[6][0]-m[1]*m[1];
            cov[1][2]=cov[2][1]=red[7][0]-m[1]*m[2];
            cov[2][2]=red[8][0]-m[2]*m[2];
        }
        __syncthreads();
        if (t < 16) {
            int o = og + t;
            float wv0=w1[o*3], wv1=w1[o*3+1], wv2=w1[o*3+2];
            float mean = wv0*m[0]+wv1*m[1]+wv2*m[2] + b1[o];
            float var = wv0*wv0*cov[0][0] + wv1*wv1*cov[1][1] + wv2*wv2*cov[2][2]
                      + 2.f*(wv0*wv1*cov[0][1] + wv0*wv2*cov[0][2] + wv1*wv2*cov[1][2]);
            float sc = g1[o]*rsqrtf(var + BEPS);
            ssc[t] = sc;
            ssh[t] = be1[o] - mean*sc;
        }
        __syncthreads();
        int n = nb*256 + t;
        float x0 = x[b*6144 + n], x1 = x[b*6144 + 2048 + n], x2 = x[b*6144 + 4096 + n];
        #pragma unroll
        for (int oo=0;oo<16;oo++) {
            int o = og + oo;
            float pre = fmaf(w1[o*3], x0, fmaf(w1[o*3+1], x1, fmaf(w1[o*3+2], x2, b1[o])));
            float h = fmaf(ssc[oo], pre, ssh[oo]);
            g_h1[(b*64+o)*2048 + n] = fmaxf(h, 0.f);
        }
    } else if (blk < 2176) {
        int blk2 = blk - 128;
        #pragma unroll
        for (int i=0;i<4;i++) {
            int id = blk2*1024 + i*256 + t;
            g_Ah[id] = __float2half_rn(w3[id]);
        }
    } else {
        if (t < 128) { g_c2sum[t] = 0.f; g_c2ss[t] = 0.f; }
    }
}

// ---------------- conv2 + BN2 + relu + transpose -> B fp16, one persistent kernel
__global__ void __launch_bounds__(256) k_conv2sb(const float* __restrict__ w2,
        const float* __restrict__ b2, const float* __restrict__ g2,
        const float* __restrict__ be2) {
    __shared__ float sbuf[8576];
    int blk = blockIdx.x, t = threadIdx.x;

    {
        float (*As)[128] = (float(*)[128])sbuf;
        float (*Bs)[128] = (float(*)[128])(sbuf + 4096);
        float* s_sum = sbuf + 8192;
        float* s_ss  = sbuf + 8320;
        int b = blk >> 4, n0 = (blk & 15)*128;
        int tx = t & 15, ty = t >> 4;
        float acc[8][8];
        #pragma unroll
        for (int r=0;r<8;r++)
            #pragma unroll
            for (int c=0;c<8;c++) acc[r][c] = 0.f;
        if (t < 128) { s_sum[t] = 0.f; s_ss[t] = 0.f; }
        for (int kc = 0; kc < 64; kc += 32) {
            __syncthreads();
            #pragma unroll
            for (int i=0;i<16;i++) { int f=t+i*256; int k=f>>7, o=f&127; As[k][o] = w2[o*64 + kc + k]; }
            #pragma unroll
            for (int i=0;i<16;i++) { int f=t+i*256; int k=f>>7, n=f&127;
                Bs[k][n] = g_h1[(b*64 + kc + k)*2048 + n0 + n]; }
            __syncthreads();
            #pragma unroll
            for (int k=0;k<32;k++) {
                float a[8], bb[8];
                *(float4*)&a[0]  = *(const float4*)&As[k][ty*8];
                *(float4*)&a[4]  = *(const float4*)&As[k][ty*8+4];
                *(float4*)&bb[0] = *(const float4*)&Bs[k][tx*8];
                *(float4*)&bb[4] = *(const float4*)&Bs[k][tx*8+4];
                #pragma unroll
                for (int r=0;r<8;r++)
                    #pragma unroll
                    for (int c=0;c<8;c++) acc[r][c] = fmaf(a[r], bb[c], acc[r][c]);
            }
        }
        #pragma unroll
        for (int r=0;r<8;r++) {
            int o = ty*8 + r;
            float bias = b2[o];
            float rs = 0.f, rq = 0.f;
            float v[8];
            #pragma unroll
            for (int c=0;c<8;c++) { v[c] = acc[r][c] + bias; rs += v[c]; rq = fmaf(v[c], v[c], rq); }
            float* dst = &g_h2[(b*128+o)*2048 + n0 + tx*8];
            *(float4*)dst     = *(float4*)&v[0];
            *(float4*)(dst+4) = *(float4*)&v[4];
            atomicAdd(&s_sum[o], rs);
            atomicAdd(&s_ss[o], rq);
        }
        __syncthreads();
        if (t < 128) { atomicAdd(&g_c2sum[t], s_sum[t]); atomicAdd(&g_c2ss[t], s_ss[t]); }
    }
    gsync(64);

    {
        float (*smv)[65] = (float(*)[65])sbuf;
        float* ssc = sbuf + 8320;
        float* ssh = sbuf + 8448;
        if (t < 128) {
            float mean = g_c2sum[t] * (1.f/8192.f);
            float var = g_c2ss[t] * (1.f/8192.f) - mean*mean;
            float sc = g2[t]*rsqrtf(var + BEPS);
            ssc[t] = sc;
            ssh[t] = be2[t] - mean*sc;
        }
        __syncthreads();
        #pragma unroll
        for (int inst_i = 0; inst_i < 2; inst_i++) {
            int inst = blk*2 + inst_i;
            int b = inst >> 5, n0 = (inst & 31)*64;
            #pragma unroll
            for (int i=0;i<32;i++) {
                int f = t + i*256; int c = f >> 6, n = f & 63;
                float v = g_h2[(b*128+c)*2048 + n0 + n];
                smv[c][n] = fmaxf(fmaf(ssc[c], v, ssh[c]), 0.f);
            }
            __syncthreads();
            int col = t & 63, q = t >> 6;
            __half* dst = g_Bs + (size_t)(b*2048 + n0 + col)*128;
            #pragma unroll
            for (int ch=0; ch<32; ch++)
                dst[q*32+ch] = __float2half_rn(smv[q*32+ch][col]);
            __syncthreads();
        }
    }
}

// ---------------- caps GEMM via mma.sync fp16: D = A · B^T, K=128 --------------
// 2 cp.async commit groups (K halves): compute ks0-3 overlaps chunk1 loads.
#define LDAH 136
#define A_BYTES (128*LDAH*2)
#define CAPS_SMEM (2*A_BYTES)

__global__ void __launch_bounds__(256,2) k_caps_mma() {
    extern __shared__ char sm[];
    const uint32_t sb = smem_u32(sm);
    const int t = threadIdx.x, w = t >> 5, lane = t & 31;
    const int row0 = blockIdx.y * 128, col0 = blockIdx.x * 128;
    const int wm = (w >> 1) * 32, wn = (w & 1) * 64;
    const int lr = lane & 7, mi = lane >> 3;

    const uint32_t aoff = ((uint32_t)(wm + (mi&1)*8 + lr)*LDAH + (mi>>1)*8) * 2;
    const uint32_t boff = ((uint32_t)(wn + (mi>>1)*8 + lr)*LDAH + (mi&1)*8) * 2;

    // chunk 0: k-halves j 0..7 for A and B
    #pragma unroll
    for (int i=0;i<4;i++) {
        int idx = t + i*256; int r = idx >> 3, j = idx & 7;
        cp16(sb + (uint32_t)(r*LDAH)*2 + j*16,
             g_Ah + (size_t)(row0 + r)*128 + j*8);
    }
    #pragma unroll
    for (int i=0;i<4;i++) {
        int idx = t + i*256; int r = idx >> 3, j = idx & 7;
        cp16(sb + A_BYTES + (uint32_t)(r*LDAH)*2 + j*16,
             g_Bs + (size_t)(col0 + r)*128 + j*8);
    }
    CP_COMMIT();
    // chunk 1: j 8..15
    #pragma unroll
    for (int i=0;i<4;i++) {
        int idx = t + i*256; int r = idx >> 3, j = (idx & 7) + 8;
        cp16(sb + (uint32_t)(r*LDAH)*2 + j*16,
             g_Ah + (size_t)(row0 + r)*128 + j*8);
    }
    #pragma unroll
    for (int i=0;i<4;i++) {
        int idx = t + i*256; int r = idx >> 3, j = (idx & 7) + 8;
        cp16(sb + A_BYTES + (uint32_t)(r*LDAH)*2 + j*16,
             g_Bs + (size_t)(col0 + r)*128 + j*8);
    }
    CP_COMMIT();

    float acc[2][8][4];
    #pragma unroll
    for (int mt=0;mt<2;mt++)
        #pragma unroll
        for (int nt=0;nt<8;nt++)
            #pragma unroll
            for (int e=0;e<4;e++) acc[mt][nt][e] = 0.f;

    CP_WAIT(1);
    __syncthreads();
    #pragma unroll
    for (int ks=0; ks<4; ks++) {
        uint32_t a[2][4];
        #pragma unroll
        for (int mt=0;mt<2;mt++)
            ldsm4(a[mt], sb + aoff + (uint32_t)(mt*16*LDAH)*2 + ks*32);
        #pragma unroll
        for (int ntp=0;ntp<4;ntp++) {
            uint32_t b[4];
            ldsm4(b, sb + A_BYTES + boff + (uint32_t)(ntp*16*LDAH)*2 + ks*32);
            #pragma unroll
            for (int mt=0;mt<2;mt++) {
                mma16816(acc[mt][ntp*2],   a[mt], b);
                mma16816(acc[mt][ntp*2+1], a[mt], b+2);
            }
        }
    }
    CP_WAIT(0);
    __syncthreads();
    #pragma unroll
    for (int ks=4; ks<8; ks++) {
        uint32_t a[2][4];
        #pragma unroll
        for (int mt=0;mt<2;mt++)
            ldsm4(a[mt], sb + aoff + (uint32_t)(mt*16*LDAH)*2 + ks*32);
        #pragma unroll
        for (int ntp=0;ntp<4;ntp++) {
            uint32_t b[4];
            ldsm4(b, sb + A_BYTES + boff + (uint32_t)(ntp*16*LDAH)*2 + ks*32);
            #pragma unroll
            for (int mt=0;mt<2;mt++) {
                mma16816(acc[mt][ntp*2],   a[mt], b);
                mma16816(acc[mt][ntp*2+1], a[mt], b+2);
            }
        }
    }
    __syncthreads();

    float4* cmb = (float4*)sm;
    #pragma unroll
    for (int mt=0;mt<2;mt++) {
        float s0=0.f,q0=0.f,mx0=-3.4028235e38f,mn0=3.4028235e38f;
        float s1=0.f,q1=0.f,mx1=-3.4028235e38f,mn1=3.4028235e38f;
        #pragma unroll
        for (int nt=0;nt<8;nt++) {
            float d0=acc[mt][nt][0], d1=acc[mt][nt][1];
            float d2=acc[mt][nt][2], d3=acc[mt][nt][3];
            s0 += d0+d1; q0 = fmaf(d0,d0,fmaf(d1,d1,q0));
            mx0 = fmaxf(mx0, fmaxf(d0,d1)); mn0 = fminf(mn0, fminf(d0,d1));
            s1 += d2+d3; q1 = fmaf(d2,d2,fmaf(d3,d3,q1));
            mx1 = fmaxf(mx1, fmaxf(d2,d3)); mn1 = fminf(mn1, fminf(d2,d3));
        }
        #pragma unroll
        for (int o=1;o<4;o<<=1) {
            s0 += __shfl_xor_sync(0xffffffffu, s0, o);
            q0 += __shfl_xor_sync(0xffffffffu, q0, o);
            mx0 = fmaxf(mx0, __shfl_xor_sync(0xffffffffu, mx0, o));
            mn0 = fminf(mn0, __shfl_xor_sync(0xffffffffu, mn0, o));
            s1 += __shfl_xor_sync(0xffffffffu, s1, o);
            q1 += __shfl_xor_sync(0xffffffffu, q1, o);
            mx1 = fmaxf(mx1, __shfl_xor_sync(0xffffffffu, mx1, o));
            mn1 = fminf(mn1, __shfl_xor_sync(0xffffffffu, mn1, o));
        }
        if ((lane & 3) == 0) {
            int r0 = wm + mt*16 + (lane >> 2);
            cmb[r0*2 + (w&1)]     = make_float4(s0, q0, mx0, mn0);
            cmb[(r0+8)*2 + (w&1)] = make_float4(s1, q1, mx1, mn1);
        }
    }
    __syncthreads();
    if (t < 128) {
        float4 a = cmb[t*2+0], b = cmb[t*2+1];
        g_pstat[(row0 + t)*64 + blockIdx.x] =
            make_float4(a.x+b.x, a.y+b.y, fmaxf(a.z,b.z), fminf(a.w,b.w));
    }
}

// ---------------- redstats + ufin, p-local blocks (no gsync) ----------------
// Block bid owns p in [bid*4, bid*4+4): all 64 rows (16 q x 4 p) block-local.
__global__ void __launch_bounds__(256) k_redufin(const float* __restrict__ b3,
        const float* __restrict__ g3, const float* __restrict__ be3) {
    int bid = blockIdx.x, t = threadIdx.x;
    __shared__ float st_s[64], st_q[64];
    __shared__ float st_mx[64][4], st_mn[64][4];
    {
        int lrw = t >> 2, qt = t & 3;            // lrw: local row 0..63
        int q = lrw >> 2, pl = lrw & 3;
        int row = q*1024 + bid*4 + pl;
        float s = 0.f, qq = 0.f;
        float mx = -3.4028235e38f, mn = 3.4028235e38f;
        const float4* ps = g_pstat + row*64 + qt*16;
        #pragma unroll
        for (int i=0;i<16;i++) {
            float4 v = ps[i];
            s += v.x; qq += v.y;
            mx = fmaxf(mx, v.z);
            mn = fminf(mn, v.w);
        }
        #pragma unroll
        for (int o=1;o<4;o<<=1) {
            s  += __shfl_xor_sync(0xffffffffu, s, o);
            qq += __shfl_xor_sync(0xffffffffu, qq, o);
        }
        float bias = b3[row];
        st_mx[lrw][qt] = mx + bias;
        st_mn[lrw][qt] = mn + bias;
        if (qt == 0) {
            st_s[lrw] = s + 8192.f*bias;
            st_q[lrw] = qq + 2.f*bias*s + 8192.f*bias*bias;
        }
    }
    __syncthreads();
    {
        int q = t & 15, item = t >> 4;           // 16 items = 4 b x 4 pl
        int b = item >> 2, pl = item & 3;
        int lrw = q*4 + pl;
        int row = q*1024 + bid*4 + pl;
        float mean = st_s[lrw]*(1.f/8192.f);
        float var  = st_q[lrw]*(1.f/8192.f) - mean*mean;
        float sc = g3[row]*rsqrtf(var + BEPS);
        float m = (sc >= 0.f) ? st_mx[lrw][b] : st_mn[lrw][b];
        float v = fmaf(sc, m - mean, be3[row]);
        float sn = v*v;
        #pragma unroll
        for (int o=1;o<16;o<<=1) sn += __shfl_xor_sync(0xffffffffu, sn, o, 16);
        float coef = sn/((1.f+sn)*sqrtf(sn));
        g_u[(b*1024 + bid*4 + pl)*16 + q] = coef*v;
    }
}

// ---------------- u_hat = einsum(lpvq,bpq->blpv), fp16, big grid ----------------
__global__ void __launch_bounds__(256) k_uhat(const float* __restrict__ Wr) {
    int gid = blockIdx.x*256 + threadIdx.x;   // 262144
    int lp = gid >> 2, vg = gid & 3;
    int l = lp >> 10, p = lp & 1023;
    float u0[16], u1[16], u2[16], u3[16];
    #pragma unroll
    for (int j=0;j<4;j++) {
        *(float4*)&u0[j*4] = *(const float4*)&g_u[(0*1024+p)*16 + j*4];
        *(float4*)&u1[j*4] = *(const float4*)&g_u[(1*1024+p)*16 + j*4];
        *(float4*)&u2[j*4] = *(const float4*)&g_u[(2*1024+p)*16 + j*4];
        *(float4*)&u3[j*4] = *(const float4*)&g_u[(3*1024+p)*16 + j*4];
    }
    const float4* wr = (const float4*)(Wr + (size_t)lp*1024 + vg*256);
    size_t obase = (((size_t)l*1024 + p)*64 + vg*16) >> 3;   // uint4 units
    uint4* o0 = (uint4*)g_uhat_h + obase;
    uint4* o1 = (uint4*)g_uhat_h + ((size_t)64*1024*64 >> 3) + obase;
    uint4* o2 = (uint4*)g_uhat_h + ((size_t)2*64*1024*64 >> 3) + obase;
    uint4* o3 = (uint4*)g_uhat_h + ((size_t)3*64*1024*64 >> 3) + obase;
    #pragma unroll
    for (int vc = 0; vc < 2; vc++) {          // 8 v per chunk
        uint32_t pk0[4], pk1[4], pk2[4], pk3[4];
        #pragma unroll
        for (int v2 = 0; v2 < 4; v2++) {
            float da[4], db[4];
            #pragma unroll
            for (int h = 0; h < 2; h++) {
                int v = vc*8 + v2*2 + h;
                float wv[16];
                *(float4*)&wv[0]  = wr[v*4+0];
                *(float4*)&wv[4]  = wr[v*4+1];
                *(float4*)&wv[8]  = wr[v*4+2];
                *(float4*)&wv[12] = wr[v*4+3];
                float d0=0.f, d1=0.f, d2=0.f, d3=0.f;
                #pragma unroll
                for (int q=0;q<16;q++) {
                    d0 = fmaf(wv[q], u0[q], d0);
                    d1 = fmaf(wv[q], u1[q], d1);
                    d2 = fmaf(wv[q], u2[q], d2);
                    d3 = fmaf(wv[q], u3[q], d3);
                }
                if (h == 0) { da[0]=d0; da[1]=d1; da[2]=d2; da[3]=d3; }
                else        { db[0]=d0; db[1]=d1; db[2]=d2; db[3]=d3; }
            }
            __half2 h0 = __floats2half2_rn(da[0], db[0]);
            __half2 h1 = __floats2half2_rn(da[1], db[1]);
            __half2 h2 = __floats2half2_rn(da[2], db[2]);
            __half2 h3 = __floats2half2_rn(da[3], db[3]);
            pk0[v2] = *(uint32_t*)&h0; pk1[v2] = *(uint32_t*)&h1;
            pk2[v2] = *(uint32_t*)&h2; pk3[v2] = *(uint32_t*)&h3;
        }
        o0[vc] = make_uint4(pk0[0],pk0[1],pk0[2],pk0[3]);
        o1[vc] = make_uint4(pk1[0],pk1[1],pk1[2],pk1[3]);
        o2[vc] = make_uint4(pk2[0],pk2[1],pk2[2],pk2[3]);
        o3[vc] = make_uint4(pk3[0],pk3[1],pk3[2],pk3[3]);
    }
}

// ---------------- persistent routing + heads ----------------
__global__ void __launch_bounds__(256) k_route(const float* __restrict__ fcw,
        const float* __restrict__ fcb, float* __restrict__ out) {
    int bid = blockIdx.x, t = threadIdx.x;
    __shared__ float cs[1024];
    __shared__ float red[8][64];
    __shared__ float sq[64];
    __shared__ float s_coef;
    __shared__ float vs[64];

    int b = bid >> 6, l = bid & 63;
    const __half2* uh = (const __half2*)(g_uhat_h + ((long)(b*64+l))*65536);
    float* bp = g_bij + (b*64+l)*1024;

    for (int it = 0; it < 3; it++) {
        // phase A: softmax normalizers (skipped for it=0: b_ij == 0 -> uniform)
        if (it > 0) {
            int item = bid*16 + (t >> 4);
            int sub = t & 15;
            int bb = item >> 10, pp = item & 1023;
            const float* bcol = g_bij + bb*65536 + pp;
            float v0 = bcol[(sub*4+0)*1024];
            float v1 = bcol[(sub*4+1)*1024];
            float v2 = bcol[(sub*4+2)*1024];
            float v3 = bcol[(sub*4+3)*1024];
            float mx = fmaxf(fmaxf(v0,v1), fmaxf(v2,v3));
            #pragma unroll
            for (int o=8;o>0;o>>=1) mx = fmaxf(mx, __shfl_down_sync(0xffffffffu, mx, o, 16));
            mx = __shfl_sync(0xffffffffu, mx, 0, 16);
            float s = __expf(v0-mx)+__expf(v1-mx)+__expf(v2-mx)+__expf(v3-mx);
            #pragma unroll
            for (int o=8;o>0;o>>=1) s += __shfl_down_sync(0xffffffffu, s, o, 16);
            if (sub == 0) { g_norm[item*2] = mx; g_norm[item*2+1] = 1.f/s; }
            gsync(256);
        }

        // phase B: v_j = squash(sum_p c*u_hat), c on the fly
        {
            int j = t & 31, pc = t >> 5;
            if (it == 0) {
                for (int i=t;i<1024;i+=256) cs[i] = 1.f/64.f;
            } else {
                for (int i=t;i<1024;i+=256) {
                    float bv = bp[i];
                    float mx = g_norm[(b*1024+i)*2], inv = g_norm[(b*1024+i)*2+1];
                    cs[i] = __expf(bv - mx) * inv;
                }
            }
            __syncthreads();
            float2 a0 = {0.f,0.f}, a1 = {0.f,0.f};
            int pb = pc*128;
            #pragma unroll 4
            for (int p = pb; p < pb+128; p += 2) {
                float2 h0 = __half22float2(uh[p*32 + j]);
                float2 h1 = __half22float2(uh[(p+1)*32 + j]);
                float c0 = cs[p], c1 = cs[p+1];
                a0.x = fmaf(c0, h0.x, a0.x); a0.y = fmaf(c0, h0.y, a0.y);
                a1.x = fmaf(c1, h1.x, a1.x); a1.y = fmaf(c1, h1.y, a1.y);
            }
            red[pc][2*j]   = a0.x + a1.x;
            red[pc][2*j+1] = a0.y + a1.y;
            __syncthreads();
            if (t < 64) {
                float vr = 0.f;
                #pragma unroll
                for (int k=0;k<8;k++) vr += red[k][t];
                red[0][t] = vr;
                sq[t] = vr*vr;
            }
            __syncthreads();
            if (t == 0) {
                float sn = 0.f;
                for (int i=0;i<64;i++) sn += sq[i];
                s_coef = sn/((1.f+sn)*sqrtf(sn));
            }
            __syncthreads();
            if (t < 64) {
                float vv = s_coef*red[0][t];
                vs[t] = vv;
                if (it == 2) g_vj[(b*64+l)*64 + t] = vv;
            }
            __syncthreads();
        }
        // fused b_ij update (iters 0,1); it=0 writes (b starts at 0, no init needed)
        if (it < 2) {
            #pragma unroll
            for (int p4 = 0; p4 < 4; p4++) {
                int p = t*4 + p4;
                const __half2* row = uh + p*32;
                float a = 0.f;
                #pragma unroll 8
                for (int j = 0; j < 32; j++) {
                    float2 h = __half22float2(row[j]);
                    a = fmaf(vs[2*j], h.x, fmaf(vs[2*j+1], h.y, a));
                }
                if (it == 0) bp[p] = a;
                else         bp[p] += a;
            }
        }
        gsync(256);
    }

    if (bid < 160) {
        int bo = bid/40, o = bid%40;
        const float* vj = g_vj + bo*4096;
        const float* wr = fcw + o*4096;
        float acc = 0.f;
        for (int i=t;i<4096;i+=256) acc = fmaf(vj[i], wr[i], acc);
        #pragma unroll
        for (int off=16;off>0;off>>=1) acc += __shfl_down_sync(0xffffffffu, acc, off);
        if ((t&31)==0) sq[t>>5] = acc;
        __syncthreads();
        if (t==0) {
            float r = 0.f;
            #pragma unroll
            for (int k=0;k<8;k++) r += sq[k];
            out[bo*40+o] = r + fcb[o];
        }
    } else if (bid < 224) {
        int w = t >> 5, lane = t & 31;
        int item = (bid-160)*4 + (w >> 1), half = w & 1;
        float v = g_vj[item*64 + half*32 + lane];
        float sv = v*v;
        #pragma unroll
        for (int off=16;off>0;off>>=1) sv += __shfl_down_sync(0xffffffffu, sv, off);
        if (lane==0) red[0][w] = sv;
        __syncthreads();
        if (t < 4) out[160 + (bid-160)*4 + t] = sqrtf(red[0][2*t] + red[0][2*t+1]);
    }
}

// ---------------- launch ----------------
extern "C" void kernel_launch(void* const* d_in, const int* in_sizes, int n_in,
                              void* d_out, int out_size) {
    const float* x   = (const float*)d_in[0];
    const float* w1  = (const float*)d_in[1];
    const float* b1  = (const float*)d_in[2];
    const float* g1  = (const float*)d_in[3];
    const float* be1 = (const float*)d_in[4];
    const float* w2  = (const float*)d_in[5];
    const float* b2  = (const float*)d_in[6];
    const float* g2  = (const float*)d_in[7];
    const float* be2 = (const float*)d_in[8];
    const float* w3  = (const float*)d_in[9];
    const float* b3  = (const float*)d_in[10];
    const float* g3  = (const float*)d_in[11];
    const float* be3 = (const float*)d_in[12];
    const float* Wr  = (const float*)d_in[13];
    const float* fcw = (const float*)d_in[14];
    const float* fcb = (const float*)d_in[15];
    float* out = (float*)d_out;

    cudaFuncSetAttribute(k_caps_mma, cudaFuncAttributeMaxDynamicSharedMemorySize, CAPS_SMEM);

    k_front<<<2177,256>>>(x,w1,b1,g1,be1,w3);          // launch 0
    k_conv2sb<<<64,256>>>(w2,b2,g2,be2);               // launch 1
    k_caps_mma<<<dim3(64,128),256,CAPS_SMEM>>>();      // launch 2
    k_redufin<<<256,256>>>(b3,g3,be3);                 // launch 3  <- profiled
    k_uhat<<<1024,256>>>(Wr);                          // launch 4
    k_route<<<256,256>>>(fcw,fcb,out);                 // launch 5
}